// round 7
// baseline (speedup 1.0000x reference)
#include <cuda_runtime.h>
#include <cuda_bf16.h>
#include <math.h>
#include <stdint.h>

// ---------------- problem constants ----------------
#define VOCAB 32000
#define EMB   512
#define SEQ   2048
#define NHEAD 8
#define NLAYER 6
#define FFDIM 2048
#define BATCH 2
#define HEADD 64
#define BT    (BATCH*SEQ)      // 4096 tokens
#define EPS_LN 1e-5f

// ---------------- scratch (device globals; no allocation allowed) ----------------
__device__ float g_h [BT*EMB];
__device__ float g_y [BT*EMB];
__device__ float g_q [BT*EMB];
__device__ float g_k [BT*EMB];
__device__ float g_v [BT*EMB];
__device__ float g_o [BT*EMB];
__device__ float g_ff[BT*FFDIM];

// ---------------- embedding ----------------
__global__ void embed_kernel(const int* __restrict__ x,
                             const float* __restrict__ tok,
                             const float* __restrict__ pos,
                             float* __restrict__ h)
{
    int row = blockIdx.x;
    int t   = row % SEQ;
    int id  = x[row];
    const float* te = tok + (size_t)id * EMB;
    const float* pe = pos + (size_t)t  * EMB;
    float* out = h + (size_t)row * EMB;
    for (int i = threadIdx.x; i < EMB; i += blockDim.x)
        out[i] = te[i] + pe[i];
}

// ---------------- layernorm ----------------
__global__ void ln_kernel(const float* __restrict__ X,
                          const float* __restrict__ scale,
                          const float* __restrict__ bias,
                          float* __restrict__ Y)
{
    int row = blockIdx.x;
    int t = threadIdx.x;                   // 128 threads
    const float* x = X + (size_t)row * EMB;
    float* y = Y + (size_t)row * EMB;

    float s = 0.f, sq = 0.f;
    #pragma unroll
    for (int i = t; i < EMB; i += 128) { float v = x[i]; s += v; sq += v*v; }

    __shared__ float r1[128], r2[128];
    r1[t] = s; r2[t] = sq;
    __syncthreads();
    for (int k = 64; k > 0; k >>= 1) {
        if (t < k) { r1[t] += r1[t+k]; r2[t] += r2[t+k]; }
        __syncthreads();
    }
    float mean = r1[0] * (1.0f/EMB);
    float var  = r2[0] * (1.0f/EMB) - mean*mean;
    float rstd = rsqrtf(var + EPS_LN);

    #pragma unroll
    for (int i = t; i < EMB; i += 128)
        y[i] = (x[i] - mean) * rstd * scale[i] + bias[i];
}

// ---------------- tf32 helpers ----------------
__device__ __forceinline__ uint32_t f2tf(float f) {
    uint32_t u; asm("cvt.rna.tf32.f32 %0, %1;" : "=r"(u) : "f"(f)); return u;
}

__device__ __forceinline__ void mma_tf32(float* c, const uint32_t* a, const uint32_t* b) {
    asm volatile(
        "mma.sync.aligned.m16n8k8.row.col.f32.tf32.tf32.f32 "
        "{%0,%1,%2,%3}, {%4,%5,%6,%7}, {%8,%9}, {%0,%1,%2,%3};\n"
        : "+f"(c[0]), "+f"(c[1]), "+f"(c[2]), "+f"(c[3])
        : "r"(a[0]), "r"(a[1]), "r"(a[2]), "r"(a[3]),
          "r"(b[0]), "r"(b[1]));
}

// ---------------- tf32 tensor-core GEMM, fragment-major smem ----------------
// Block tile 128x128x32, 256 threads = 8 warps (2 along M x 4 along N),
// warp tile 64x32 = 4x4 m16n8k8 tiles. Double-buffered smem.
// Smem holds MMA FRAGMENTS, not matrices:
//   A element (m,k):  block (m>>4)*4 + (k>>3) [ABLK words], word
//                     ((m>>3)&1) + 2*((k>>2)&1), lane (m&7)*4 + (k&3)
//   W element (k,n):  block (n>>3)*4 + (k>>3) [BBLK words], word
//                     ((k>>2)&1), lane (n&7)*4 + (k&3)
// so a fragment load is ONE LDS.128 (A) / LDS.64 (W) per mma tile.
#define ABLK 136   // 128 + pad (mod32=8 spreads staging banks)
#define BBLK 68    // 64 + pad  (mod32=4)
#define STG_WORDS (32*ABLK + 64*BBLK)          // 8704 words / stage
#define GEMM_SMEM_BYTES (2*STG_WORDS*4)        // 69632 B

template<bool RELU, bool RES>
__device__ __forceinline__ void gemm_core(
    const float* __restrict__ A,
    const float* __restrict__ W,
    const float* __restrict__ bias,
    float* __restrict__ C,
    int M, int N, int K, int bx, int by, uint32_t* dsm)
{
    const int tid  = threadIdx.x;
    const int warp = tid >> 5, lane = tid & 31;
    const int m0   = (warp & 1) * 64;
    const int n0   = (warp >> 1) * 32;
    const int mtb  = (warp & 1) * 4;      // mtile base
    const int ntb  = (warp >> 1) * 4;     // ntile base
    const int group = lane >> 2, tcol = lane & 3;

    // staging indices
    const int aRow  = tid >> 3;           // 0..31 (+32*i)
    const int aCol  = (tid & 7) << 2;     // 0..28
    const int aKt   = (tid & 7) >> 1;
    const int aWk   = ((tid & 7) & 1) * 2;
    const int wRow  = tid >> 3;           // k: 0..31
    const int wColq = (tid & 7) << 2;     // n base within 32-chunk (+32*i)
    const int wK8t  = wRow >> 3;
    const int wWk   = (wRow >> 2) & 1;
    const int wLane2 = (wRow & 3);

    float c[4][4][4];
    #pragma unroll
    for (int mt = 0; mt < 4; mt++)
        #pragma unroll
        for (int nt = 0; nt < 4; nt++)
            #pragma unroll
            for (int j = 0; j < 4; j++) c[mt][nt][j] = 0.f;

    const int ktiles = K >> 5;
    float4 pa[4], pw[4];

    // ---- prologue: k-tile 0 global loads ----
    #pragma unroll
    for (int i = 0; i < 4; i++)
        pa[i] = *(const float4*)&A[(size_t)(by*128 + aRow + i*32)*K + aCol];
    #pragma unroll
    for (int i = 0; i < 4; i++)
        pw[i] = *(const float4*)&W[(size_t)wRow*N + bx*128 + wColq + i*32];

    // stage 0
    {
        uint32_t* As0 = dsm;
        uint32_t* Ws0 = dsm + 32*ABLK;
        #pragma unroll
        for (int i = 0; i < 4; i++) {
            int m = aRow + i*32;
            uint32_t ab = (uint32_t)(((m>>4)*4 + aKt)*ABLK + (m&7)*16 + ((m>>3)&1) + aWk);
            As0[ab   ] = f2tf(pa[i].x);
            As0[ab+ 4] = f2tf(pa[i].y);
            As0[ab+ 8] = f2tf(pa[i].z);
            As0[ab+12] = f2tf(pa[i].w);
        }
        #pragma unroll
        for (int i = 0; i < 4; i++) {
            int n = wColq + i*32;
            uint32_t bb = (uint32_t)(((n>>3)*4 + wK8t)*BBLK + (((n&7)*4 + wLane2)*2) + wWk);
            Ws0[bb    ] = f2tf(pw[i].x);
            Ws0[bb+  8] = f2tf(pw[i].y);
            Ws0[bb+ 16] = f2tf(pw[i].z);
            Ws0[bb+ 24] = f2tf(pw[i].w);
        }
    }

    int s = 0;
    for (int kt = 0; kt < ktiles; kt++) {
        __syncthreads();

        const bool more = (kt + 1 < ktiles);
        if (more) {
            const int kb = (kt + 1) << 5;
            #pragma unroll
            for (int i = 0; i < 4; i++)
                pa[i] = *(const float4*)&A[(size_t)(by*128 + aRow + i*32)*K + kb + aCol];
            #pragma unroll
            for (int i = 0; i < 4; i++)
                pw[i] = *(const float4*)&W[(size_t)(kb + wRow)*N + bx*128 + wColq + i*32];
        }

        // ---- compute from stage s: one LDS.128 per A tile, LDS.64 per W tile ----
        const uint32_t* Ass = dsm + s*STG_WORDS;
        const uint32_t* Wss = Ass + 32*ABLK;
        #pragma unroll
        for (int ks = 0; ks < 4; ks++) {
            uint4 af[4]; uint2 bf[4];
            #pragma unroll
            for (int mt = 0; mt < 4; mt++)
                af[mt] = *(const uint4*)&Ass[((mtb+mt)*4 + ks)*ABLK + lane*4];
            #pragma unroll
            for (int nt = 0; nt < 4; nt++)
                bf[nt] = *(const uint2*)&Wss[((ntb+nt)*4 + ks)*BBLK + lane*2];
            #pragma unroll
            for (int mt = 0; mt < 4; mt++)
                #pragma unroll
                for (int nt = 0; nt < 4; nt++)
                    mma_tf32(c[mt][nt], (const uint32_t*)&af[mt], (const uint32_t*)&bf[nt]);
        }

        // ---- stage next tile ----
        if (more) {
            uint32_t* As2 = dsm + (s^1)*STG_WORDS;
            uint32_t* Ws2 = As2 + 32*ABLK;
            #pragma unroll
            for (int i = 0; i < 4; i++) {
                int m = aRow + i*32;
                uint32_t ab = (uint32_t)(((m>>4)*4 + aKt)*ABLK + (m&7)*16 + ((m>>3)&1) + aWk);
                As2[ab   ] = f2tf(pa[i].x);
                As2[ab+ 4] = f2tf(pa[i].y);
                As2[ab+ 8] = f2tf(pa[i].z);
                As2[ab+12] = f2tf(pa[i].w);
            }
            #pragma unroll
            for (int i = 0; i < 4; i++) {
                int n = wColq + i*32;
                uint32_t bb = (uint32_t)(((n>>3)*4 + wK8t)*BBLK + (((n&7)*4 + wLane2)*2) + wWk);
                Ws2[bb    ] = f2tf(pw[i].x);
                Ws2[bb+  8] = f2tf(pw[i].y);
                Ws2[bb+ 16] = f2tf(pw[i].z);
                Ws2[bb+ 24] = f2tf(pw[i].w);
            }
        }
        s ^= 1;
    }

    // ---- epilogue (identical to R5) ----
    #pragma unroll
    for (int mt = 0; mt < 4; mt++) {
        #pragma unroll
        for (int nt = 0; nt < 4; nt++) {
            const int col = bx*128 + n0 + nt*8 + tcol*2;
            float2 bb = *(const float2*)&bias[col];
            #pragma unroll
            for (int r = 0; r < 2; r++) {
                const int row = by*128 + m0 + mt*16 + group + r*8;
                float2 v;
                v.x = c[mt][nt][r*2+0] + bb.x;
                v.y = c[mt][nt][r*2+1] + bb.y;
                if (RELU) { v.x = fmaxf(v.x, 0.f); v.y = fmaxf(v.y, 0.f); }
                float2* cp = (float2*)&C[(size_t)row*N + col];
                if (RES) { float2 o = *cp; v.x += o.x; v.y += o.y; }
                *cp = v;
            }
        }
    }
}

template<bool RELU, bool RES>
__global__ __launch_bounds__(256, 2) void gemm128(
    int M, int N, int K,
    const float* __restrict__ A,
    const float* __restrict__ W,
    const float* __restrict__ bias,
    float* __restrict__ C)
{
    extern __shared__ uint32_t dsm[];
    gemm_core<RELU,RES>(A, W, bias, C, M, N, K, blockIdx.x, blockIdx.y, dsm);
}

__global__ __launch_bounds__(256, 2) void qkv_gemm(
    const float* __restrict__ A,
    const float* __restrict__ Wq, const float* __restrict__ Wk, const float* __restrict__ Wv,
    const float* __restrict__ bq, const float* __restrict__ bk, const float* __restrict__ bv,
    float* __restrict__ q, float* __restrict__ k, float* __restrict__ v)
{
    extern __shared__ uint32_t dsm[];
    const int w   = blockIdx.x >> 2;
    const int nbx = blockIdx.x & 3;
    const float* W = (w == 0) ? Wq : (w == 1) ? Wk : Wv;
    const float* b = (w == 0) ? bq : (w == 1) ? bk : bv;
    float*       C = (w == 0) ? q  : (w == 1) ? k  : v;
    gemm_core<false,false>(A, W, b, C, BT, EMB, EMB, nbx, blockIdx.y, dsm);
}

// ---------------- tensor-core flash attention (unchanged, known-good) ----------------
#define QS_STRIDE 68
#define KS_STRIDE 68
#define VS_STRIDE 72
#define PS_STRIDE 68
#define ATT_SMEM_WORDS (128*QS_STRIDE + 64*KS_STRIDE + 64*VS_STRIDE)
#define ATT_SMEM_BYTES (ATT_SMEM_WORDS*4)

__global__ __launch_bounds__(256, 2) void attn_mma_kernel(
        const float* __restrict__ Q,
        const float* __restrict__ K,
        const float* __restrict__ V,
        float* __restrict__ O)
{
    extern __shared__ uint32_t smw[];
    uint32_t* qs = smw;
    uint32_t* ks = qs + 128*QS_STRIDE;
    uint32_t* vs = ks + 64*KS_STRIDE;
    uint32_t* ps = qs;

    const int bq = blockIdx.x, hh = blockIdx.y, bb = blockIdx.z;
    const int tid = threadIdx.x, warp = tid >> 5, lane = tid & 31;
    const int g = lane >> 2, tc = lane & 3;
    const int wq = warp * 16;

    const size_t base = ((size_t)bb*SEQ)*EMB + (size_t)hh*HEADD;

    #pragma unroll
    for (int i = 0; i < 8; i++) {
        int f   = i*256 + tid;
        int row = f >> 4, d4 = (f & 15) << 2;
        float4 v = *(const float4*)&Q[base + (size_t)(bq*128 + row)*EMB + d4];
        uint4 u = { f2tf(v.x*0.125f), f2tf(v.y*0.125f), f2tf(v.z*0.125f), f2tf(v.w*0.125f) };
        *(uint4*)&qs[row*QS_STRIDE + d4] = u;
    }
    __syncthreads();

    uint32_t qf[8][4];
    #pragma unroll
    for (int ki = 0; ki < 8; ki++) {
        int k0 = ki*8;
        qf[ki][0] = qs[(wq+g  )*QS_STRIDE + k0 + tc];
        qf[ki][1] = qs[(wq+g+8)*QS_STRIDE + k0 + tc];
        qf[ki][2] = qs[(wq+g  )*QS_STRIDE + k0 + tc + 4];
        qf[ki][3] = qs[(wq+g+8)*QS_STRIDE + k0 + tc + 4];
    }

    float o[8][4];
    #pragma unroll
    for (int nt = 0; nt < 8; nt++)
        #pragma unroll
        for (int j = 0; j < 4; j++) o[nt][j] = 0.f;
    float m0 = -1e30f, m1 = -1e30f, l0 = 0.f, l1 = 0.f;

    const int nkt = 2*bq + 2;
    for (int kt = 0; kt < nkt; kt++) {
        __syncthreads();

        #pragma unroll
        for (int i = 0; i < 4; i++) {
            int f   = i*256 + tid;
            int tok = f >> 4, d4 = (f & 15) << 2;
            float4 kv = *(const float4*)&K[base + (size_t)(kt*64 + tok)*EMB + d4];
            uint4 uk = { f2tf(kv.x), f2tf(kv.y), f2tf(kv.z), f2tf(kv.w) };
            *(uint4*)&ks[tok*KS_STRIDE + d4] = uk;
            float4 vv = *(const float4*)&V[base + (size_t)(kt*64 + tok)*EMB + d4];
            uint4 uv = { f2tf(vv.x), f2tf(vv.y), f2tf(vv.z), f2tf(vv.w) };
            *(uint4*)&vs[tok*VS_STRIDE + d4] = uv;
        }
        __syncthreads();

        float sc[8][4];
        #pragma unroll
        for (int nt = 0; nt < 8; nt++)
            #pragma unroll
            for (int j = 0; j < 4; j++) sc[nt][j] = 0.f;

        #pragma unroll
        for (int ki = 0; ki < 8; ki++) {
            int k0 = ki*8;
            uint32_t bf[8][2];
            #pragma unroll
            for (int nt = 0; nt < 8; nt++) {
                int nb = nt*8 + g;
                bf[nt][0] = ks[nb*KS_STRIDE + k0 + tc];
                bf[nt][1] = ks[nb*KS_STRIDE + k0 + tc + 4];
            }
            #pragma unroll
            for (int nt = 0; nt < 8; nt++)
                mma_tf32(sc[nt], qf[ki], bf[nt]);
        }

        if (kt >= 2*bq) {
            const int row0 = bq*128 + wq + g;
            #pragma unroll
            for (int nt = 0; nt < 8; nt++) {
                int c0 = kt*64 + nt*8 + 2*tc;
                if (c0     > row0    ) sc[nt][0] = -1e30f;
                if (c0 + 1 > row0    ) sc[nt][1] = -1e30f;
                if (c0     > row0 + 8) sc[nt][2] = -1e30f;
                if (c0 + 1 > row0 + 8) sc[nt][3] = -1e30f;
            }
        }

        float r0 = -1e30f, r1 = -1e30f;
        #pragma unroll
        for (int nt = 0; nt < 8; nt++) {
            r0 = fmaxf(r0, fmaxf(sc[nt][0], sc[nt][1]));
            r1 = fmaxf(r1, fmaxf(sc[nt][2], sc[nt][3]));
        }
        r0 = fmaxf(r0, __shfl_xor_sync(0xffffffffu, r0, 1));
        r0 = fmaxf(r0, __shfl_xor_sync(0xffffffffu, r0, 2));
        r1 = fmaxf(r1, __shfl_xor_sync(0xffffffffu, r1, 1));
        r1 = fmaxf(r1, __shfl_xor_sync(0xffffffffu, r1, 2));

        float mn0 = fmaxf(m0, r0), mn1 = fmaxf(m1, r1);
        float cor0 = __expf(m0 - mn0), cor1 = __expf(m1 - mn1);
        m0 = mn0; m1 = mn1;
        l0 *= cor0; l1 *= cor1;
        #pragma unroll
        for (int nt = 0; nt < 8; nt++) {
            o[nt][0] *= cor0; o[nt][1] *= cor0;
            o[nt][2] *= cor1; o[nt][3] *= cor1;
        }

        float s0 = 0.f, s1 = 0.f;
        #pragma unroll
        for (int nt = 0; nt < 8; nt++) {
            float p00 = __expf(sc[nt][0] - mn0);
            float p01 = __expf(sc[nt][1] - mn0);
            float p10 = __expf(sc[nt][2] - mn1);
            float p11 = __expf(sc[nt][3] - mn1);
            s0 += p00 + p01; s1 += p10 + p11;
            int col = nt*8 + 2*tc;
            ps[(wq+g  )*PS_STRIDE + col    ] = f2tf(p00);
            ps[(wq+g  )*PS_STRIDE + col + 1] = f2tf(p01);
            ps[(wq+g+8)*PS_STRIDE + col    ] = f2tf(p10);
            ps[(wq+g+8)*PS_STRIDE + col + 1] = f2tf(p11);
        }
        s0 += __shfl_xor_sync(0xffffffffu, s0, 1);
        s0 += __shfl_xor_sync(0xffffffffu, s0, 2);
        s1 += __shfl_xor_sync(0xffffffffu, s1, 1);
        s1 += __shfl_xor_sync(0xffffffffu, s1, 2);
        l0 += s0; l1 += s1;
        __syncwarp();

        #pragma unroll
        for (int ki = 0; ki < 8; ki++) {
            int k0 = ki*8;
            uint32_t af[4];
            af[0] = ps[(wq+g  )*PS_STRIDE + k0 + tc];
            af[1] = ps[(wq+g+8)*PS_STRIDE + k0 + tc];
            af[2] = ps[(wq+g  )*PS_STRIDE + k0 + tc + 4];
            af[3] = ps[(wq+g+8)*PS_STRIDE + k0 + tc + 4];
            uint32_t bf[8][2];
            #pragma unroll
            for (int nt = 0; nt < 8; nt++) {
                int nb = nt*8 + g;
                bf[nt][0] = vs[(k0 + tc    )*VS_STRIDE + nb];
                bf[nt][1] = vs[(k0 + tc + 4)*VS_STRIDE + nb];
            }
            #pragma unroll
            for (int nt = 0; nt < 8; nt++)
                mma_tf32(o[nt], af, bf[nt]);
        }
        __syncwarp();
    }

    float inv0 = 1.0f / l0, inv1 = 1.0f / l1;
    const int row0 = bq*128 + wq + g;
    #pragma unroll
    for (int nt = 0; nt < 8; nt++) {
        int d = nt*8 + 2*tc;
        float2 a; a.x = o[nt][0]*inv0; a.y = o[nt][1]*inv0;
        *(float2*)&O[base + (size_t)row0*EMB + d] = a;
        float2 b; b.x = o[nt][2]*inv1; b.y = o[nt][3]*inv1;
        *(float2*)&O[base + (size_t)(row0+8)*EMB + d] = b;
    }
}

// ---------------- orchestration ----------------
extern "C" void kernel_launch(void* const* d_in, const int* in_sizes, int n_in,
                              void* d_out, int out_size)
{
    (void)in_sizes; (void)n_in;
    const int*   x       = (const int*)  d_in[0];
    const float* tok_emb = (const float*)d_in[1];
    const float* pos_emb = (const float*)d_in[2];
    const float* Wq   = (const float*)d_in[3];
    const float* bq   = (const float*)d_in[4];
    const float* Wk   = (const float*)d_in[5];
    const float* bk   = (const float*)d_in[6];
    const float* Wv   = (const float*)d_in[7];
    const float* bv   = (const float*)d_in[8];
    const float* Wo   = (const float*)d_in[9];
    const float* bo   = (const float*)d_in[10];
    const float* ln1s = (const float*)d_in[11];
    const float* ln1b = (const float*)d_in[12];
    const float* ln2s = (const float*)d_in[13];
    const float* ln2b = (const float*)d_in[14];
    const float* W1   = (const float*)d_in[15];
    const float* b1   = (const float*)d_in[16];
    const float* W2   = (const float*)d_in[17];
    const float* b2   = (const float*)d_in[18];
    const float* Wout = (const float*)d_in[19];
    const float* bout = (const float*)d_in[20];
    float* out = (float*)d_out;
    (void)out_size;

    float *h, *y, *q, *k, *v, *o, *ff;
    cudaGetSymbolAddress((void**)&h,  g_h);
    cudaGetSymbolAddress((void**)&y,  g_y);
    cudaGetSymbolAddress((void**)&q,  g_q);
    cudaGetSymbolAddress((void**)&k,  g_k);
    cudaGetSymbolAddress((void**)&v,  g_v);
    cudaGetSymbolAddress((void**)&o,  g_o);
    cudaGetSymbolAddress((void**)&ff, g_ff);

    cudaFuncSetAttribute(gemm128<false,false>,
        cudaFuncAttributeMaxDynamicSharedMemorySize, GEMM_SMEM_BYTES);
    cudaFuncSetAttribute(gemm128<false,true>,
        cudaFuncAttributeMaxDynamicSharedMemorySize, GEMM_SMEM_BYTES);
    cudaFuncSetAttribute(gemm128<true,false>,
        cudaFuncAttributeMaxDynamicSharedMemorySize, GEMM_SMEM_BYTES);
    cudaFuncSetAttribute(qkv_gemm,
        cudaFuncAttributeMaxDynamicSharedMemorySize, GEMM_SMEM_BYTES);
    cudaFuncSetAttribute(attn_mma_kernel,
        cudaFuncAttributeMaxDynamicSharedMemorySize, ATT_SMEM_BYTES);

    const int M = BT;
    embed_kernel<<<BT, 128>>>(x, tok_emb, pos_emb, h);

    for (int i = 0; i < NLAYER; i++) {
        const float* Wqi = Wq + (size_t)i*EMB*EMB;
        const float* Wki = Wk + (size_t)i*EMB*EMB;
        const float* Wvi = Wv + (size_t)i*EMB*EMB;
        const float* Woi = Wo + (size_t)i*EMB*EMB;
        const float* W1i = W1 + (size_t)i*EMB*FFDIM;
        const float* W2i = W2 + (size_t)i*FFDIM*EMB;

        ln_kernel<<<BT, 128>>>(h, ln1s + i*EMB, ln1b + i*EMB, y);

        qkv_gemm<<<dim3(12, M/128), 256, GEMM_SMEM_BYTES>>>(
            y, Wqi, Wki, Wvi, bq + i*EMB, bk + i*EMB, bv + i*EMB, q, k, v);

        attn_mma_kernel<<<dim3(SEQ/128, NHEAD, BATCH), 256, ATT_SMEM_BYTES>>>(q, k, v, o);

        gemm128<false,true><<<dim3(EMB/128, M/128), 256, GEMM_SMEM_BYTES>>>(
            M, EMB, EMB, o, Woi, bo + i*EMB, h);

        ln_kernel<<<BT, 128>>>(h, ln2s + i*EMB, ln2b + i*EMB, y);

        gemm128<true,false><<<dim3(FFDIM/128, M/128), 256, GEMM_SMEM_BYTES>>>(
            M, FFDIM, EMB, y, W1i, b1 + i*FFDIM, ff);

        gemm128<false,true><<<dim3(EMB/128, M/128), 256, GEMM_SMEM_BYTES>>>(
            M, EMB, FFDIM, ff, W2i, b2 + i*EMB, h);
    }

    gemm128<false,false><<<dim3(VOCAB/128, M/128), 256, GEMM_SMEM_BYTES>>>(
        M, VOCAB, EMB, h, Wout, bout, out);
}

// round 8
// speedup vs baseline: 1.2400x; 1.2400x over previous
#include <cuda_runtime.h>
#include <cuda_bf16.h>
#include <math.h>
#include <stdint.h>

// ---------------- problem constants ----------------
#define VOCAB 32000
#define EMB   512
#define SEQ   2048
#define NHEAD 8
#define NLAYER 6
#define FFDIM 2048
#define BATCH 2
#define HEADD 64
#define BT    (BATCH*SEQ)      // 4096 tokens
#define EPS_LN 1e-5f

// ---------------- scratch (device globals; no allocation allowed) ----------------
__device__ float    g_h  [BT*EMB];     // residual stream (fp32)
__device__ uint32_t g_y  [BT*EMB];     // LN output (tf32)
__device__ uint32_t g_q  [BT*EMB];     // tf32, pre-scaled by 0.125
__device__ uint32_t g_k  [BT*EMB];     // tf32
__device__ uint32_t g_v  [BT*EMB];     // tf32
__device__ uint32_t g_o  [BT*EMB];     // attention output (tf32)
__device__ uint32_t g_ff [BT*FFDIM];   // FFN hidden (tf32)
__device__ uint32_t g_htf[BT*EMB];     // final residual (tf32) for vocab gemm

// tf32 weight mirror, same [K][N] layout as inputs
#define EE6 (NLAYER*EMB*EMB)
#define EF6 (NLAYER*EMB*FFDIM)
#define OFF_WQ   0
#define OFF_WK   (EE6)
#define OFF_WV   (2*EE6)
#define OFF_WO   (3*EE6)
#define OFF_W1   (4*EE6)
#define OFF_W2   (4*EE6 + EF6)
#define OFF_WOUT (4*EE6 + 2*EF6)
#define WTF_TOTAL (4*EE6 + 2*EF6 + EMB*VOCAB)
__device__ uint32_t g_wtf[WTF_TOTAL];

// ---------------- tf32 helpers ----------------
__device__ __forceinline__ uint32_t f2tf(float f) {
    uint32_t u; asm("cvt.rna.tf32.f32 %0, %1;" : "=r"(u) : "f"(f)); return u;
}
__device__ __forceinline__ void mma_tf32(float* c, const uint32_t* a, const uint32_t* b) {
    asm volatile(
        "mma.sync.aligned.m16n8k8.row.col.f32.tf32.tf32.f32 "
        "{%0,%1,%2,%3}, {%4,%5,%6,%7}, {%8,%9}, {%0,%1,%2,%3};\n"
        : "+f"(c[0]), "+f"(c[1]), "+f"(c[2]), "+f"(c[3])
        : "r"(a[0]), "r"(a[1]), "r"(a[2]), "r"(a[3]),
          "r"(b[0]), "r"(b[1]));
}

// ---------------- one-time weight convert fp32 -> tf32 ----------------
__global__ void cvt_tf_kernel(const float* __restrict__ s, uint32_t* __restrict__ d, int n)
{
    int i = (blockIdx.x * 256 + threadIdx.x) * 4;
    if (i < n) {
        float4 v = *(const float4*)&s[i];
        uint4 u = { f2tf(v.x), f2tf(v.y), f2tf(v.z), f2tf(v.w) };
        *(uint4*)&d[i] = u;
    }
}

// ---------------- embedding ----------------
__global__ void embed_kernel(const int* __restrict__ x,
                             const float* __restrict__ tok,
                             const float* __restrict__ pos,
                             float* __restrict__ h)
{
    int row = blockIdx.x;
    int t   = row % SEQ;
    int id  = x[row];
    const float* te = tok + (size_t)id * EMB;
    const float* pe = pos + (size_t)t  * EMB;
    float* out = h + (size_t)row * EMB;
    for (int i = threadIdx.x; i < EMB; i += blockDim.x)
        out[i] = te[i] + pe[i];
}

// ---------------- layernorm (emits tf32 directly) ----------------
__global__ void ln_kernel(const float* __restrict__ X,
                          const float* __restrict__ scale,
                          const float* __restrict__ bias,
                          uint32_t* __restrict__ Y)
{
    int row = blockIdx.x;
    int t = threadIdx.x;                   // 128 threads
    const float* x = X + (size_t)row * EMB;
    uint32_t* y = Y + (size_t)row * EMB;

    float s = 0.f, sq = 0.f;
    #pragma unroll
    for (int i = t; i < EMB; i += 128) { float v = x[i]; s += v; sq += v*v; }

    __shared__ float r1[128], r2[128];
    r1[t] = s; r2[t] = sq;
    __syncthreads();
    for (int k = 64; k > 0; k >>= 1) {
        if (t < k) { r1[t] += r1[t+k]; r2[t] += r2[t+k]; }
        __syncthreads();
    }
    float mean = r1[0] * (1.0f/EMB);
    float var  = r2[0] * (1.0f/EMB) - mean*mean;
    float rstd = rsqrtf(var + EPS_LN);

    #pragma unroll
    for (int i = t; i < EMB; i += 128)
        y[i] = f2tf((x[i] - mean) * rstd * scale[i] + bias[i]);
}

// ---------------- tf32 tensor-core GEMM (3433-baseline layout, tf32-in staging) ----------------
// Block tile 128x128x32, 256 threads = 8 warps (2 along M x 4 along N),
// warp tile 64x32 = 4x4 m16n8k8 tiles. Double-buffered smem.
// A, W already tf32 in gmem -> staging is LDG.128 + STS.128, zero cvt.
// TFM: 0 = fp32 C only, 1 = tf32 Ctf only, 2 = both.
#define APAD 36    // A row stride: frag banks (4g+t)%32 distinct
#define WPAD 136   // W row stride: mod32=8 -> frag banks (8t+g)%32 distinct
#define GEMM_SMEM_BYTES ((2*128*APAD + 2*32*WPAD)*4)   // 71680 B

template<bool RELU, bool RES, int TFM>
__device__ __forceinline__ void gemm_core(
    const uint32_t* __restrict__ A,
    const uint32_t* __restrict__ W,
    const float* __restrict__ bias,
    float* __restrict__ C,
    uint32_t* __restrict__ Ctf,
    float tfscale,
    int M, int N, int K, int bx, int by, uint32_t* dsm)
{
    uint32_t (*As)[128][APAD] = (uint32_t(*)[128][APAD])dsm;
    uint32_t (*Ws)[32][WPAD]  = (uint32_t(*)[32][WPAD])(dsm + 2*128*APAD);

    const int tid  = threadIdx.x;
    const int warp = tid >> 5, lane = tid & 31;
    const int m0   = (warp & 1) * 64;
    const int n0   = (warp >> 1) * 32;
    const int group = lane >> 2, tcol = lane & 3;

    const int aRow = tid >> 3;
    const int aCol = (tid & 7) << 2;
    const int wRow = tid >> 3;
    const int wCol = (tid & 7) << 2;

    float c[4][4][4];
    #pragma unroll
    for (int mt = 0; mt < 4; mt++)
        #pragma unroll
        for (int nt = 0; nt < 4; nt++)
            #pragma unroll
            for (int j = 0; j < 4; j++) c[mt][nt][j] = 0.f;

    const int ktiles = K >> 5;
    uint4 pa[4], pw[4];

    // ---- prologue: k-tile 0 ----
    #pragma unroll
    for (int i = 0; i < 4; i++)
        pa[i] = *(const uint4*)&A[(size_t)(by*128 + aRow + i*32)*K + aCol];
    #pragma unroll
    for (int i = 0; i < 4; i++)
        pw[i] = *(const uint4*)&W[(size_t)wRow*N + bx*128 + wCol + i*32];

    #pragma unroll
    for (int i = 0; i < 4; i++)
        *(uint4*)&As[0][aRow + i*32][aCol] = pa[i];
    #pragma unroll
    for (int i = 0; i < 4; i++)
        *(uint4*)&Ws[0][wRow][wCol + i*32] = pw[i];

    int s = 0;
    for (int kt = 0; kt < ktiles; kt++) {
        __syncthreads();

        const bool more = (kt + 1 < ktiles);
        if (more) {
            const int kb = (kt + 1) << 5;
            #pragma unroll
            for (int i = 0; i < 4; i++)
                pa[i] = *(const uint4*)&A[(size_t)(by*128 + aRow + i*32)*K + kb + aCol];
            #pragma unroll
            for (int i = 0; i < 4; i++)
                pw[i] = *(const uint4*)&W[(size_t)(kb + wRow)*N + bx*128 + wCol + i*32];
        }

        #pragma unroll
        for (int ks = 0; ks < 4; ks++) {
            const int k0 = ks << 3;
            uint32_t af[4][4], bf[4][2];
            #pragma unroll
            for (int mt = 0; mt < 4; mt++) {
                const int mb = m0 + mt*16 + group;
                af[mt][0] = As[s][mb    ][k0 + tcol];
                af[mt][1] = As[s][mb + 8][k0 + tcol];
                af[mt][2] = As[s][mb    ][k0 + tcol + 4];
                af[mt][3] = As[s][mb + 8][k0 + tcol + 4];
            }
            #pragma unroll
            for (int nt = 0; nt < 4; nt++) {
                const int nb = n0 + nt*8 + group;
                bf[nt][0] = Ws[s][k0 + tcol    ][nb];
                bf[nt][1] = Ws[s][k0 + tcol + 4][nb];
            }
            #pragma unroll
            for (int mt = 0; mt < 4; mt++)
                #pragma unroll
                for (int nt = 0; nt < 4; nt++)
                    mma_tf32(c[mt][nt], af[mt], bf[nt]);
        }

        if (more) {
            const int s2 = s ^ 1;
            #pragma unroll
            for (int i = 0; i < 4; i++)
                *(uint4*)&As[s2][aRow + i*32][aCol] = pa[i];
            #pragma unroll
            for (int i = 0; i < 4; i++)
                *(uint4*)&Ws[s2][wRow][wCol + i*32] = pw[i];
        }
        s ^= 1;
    }

    // ---- epilogue ----
    #pragma unroll
    for (int mt = 0; mt < 4; mt++) {
        #pragma unroll
        for (int nt = 0; nt < 4; nt++) {
            const int col = bx*128 + n0 + nt*8 + tcol*2;
            float2 bb = *(const float2*)&bias[col];
            #pragma unroll
            for (int r = 0; r < 2; r++) {
                const int row = by*128 + m0 + mt*16 + group + r*8;
                float2 v;
                v.x = c[mt][nt][r*2+0] + bb.x;
                v.y = c[mt][nt][r*2+1] + bb.y;
                if (RELU) { v.x = fmaxf(v.x, 0.f); v.y = fmaxf(v.y, 0.f); }
                float2* cp = (float2*)&C[(size_t)row*N + col];
                if (RES) { float2 o = *cp; v.x += o.x; v.y += o.y; }
                if (TFM != 1) *cp = v;
                if (TFM >= 1) {
                    uint2 t2 = { f2tf(v.x * tfscale), f2tf(v.y * tfscale) };
                    *(uint2*)&Ctf[(size_t)row*N + col] = t2;
                }
            }
        }
    }
}

template<bool RELU, bool RES, int TFM>
__global__ __launch_bounds__(256) void gemm128(
    int M, int N, int K,
    const uint32_t* __restrict__ A,
    const uint32_t* __restrict__ W,
    const float* __restrict__ bias,
    float* __restrict__ C,
    uint32_t* __restrict__ Ctf)
{
    extern __shared__ uint32_t dsm[];
    gemm_core<RELU,RES,TFM>(A, W, bias, C, Ctf, 1.0f, M, N, K, blockIdx.x, blockIdx.y, dsm);
}

// fused QKV: grid.x = 12 (3 weights x 4 N-tiles); outputs tf32 only, q pre-scaled.
__global__ __launch_bounds__(256) void qkv_gemm(
    const uint32_t* __restrict__ A,
    const uint32_t* __restrict__ Wq, const uint32_t* __restrict__ Wk, const uint32_t* __restrict__ Wv,
    const float* __restrict__ bq, const float* __restrict__ bk, const float* __restrict__ bv,
    uint32_t* __restrict__ q, uint32_t* __restrict__ k, uint32_t* __restrict__ v)
{
    extern __shared__ uint32_t dsm[];
    const int w   = blockIdx.x >> 2;
    const int nbx = blockIdx.x & 3;
    const uint32_t* W = (w == 0) ? Wq : (w == 1) ? Wk : Wv;
    const float*    b = (w == 0) ? bq : (w == 1) ? bk : bv;
    uint32_t*       C = (w == 0) ? q  : (w == 1) ? k  : v;
    const float    sc = (w == 0) ? 0.125f : 1.0f;
    gemm_core<false,false,1>(A, W, b, nullptr, C, sc, BT, EMB, EMB, nbx, blockIdx.y, dsm);
}

// ---------------- tensor-core flash attention (tf32 inputs, tf32 output) ----------------
#define QS_STRIDE 68
#define KS_STRIDE 68
#define VS_STRIDE 72
#define PS_STRIDE 68
#define ATT_SMEM_WORDS (128*QS_STRIDE + 64*KS_STRIDE + 64*VS_STRIDE)
#define ATT_SMEM_BYTES (ATT_SMEM_WORDS*4)

__global__ __launch_bounds__(256, 2) void attn_mma_kernel(
        const uint32_t* __restrict__ Q,   // tf32, pre-scaled by 0.125
        const uint32_t* __restrict__ K,   // tf32
        const uint32_t* __restrict__ V,   // tf32
        uint32_t* __restrict__ O)         // tf32 out
{
    extern __shared__ uint32_t smw[];
    uint32_t* qs = smw;
    uint32_t* ks = qs + 128*QS_STRIDE;
    uint32_t* vs = ks + 64*KS_STRIDE;
    uint32_t* ps = qs;

    const int bq = blockIdx.x, hh = blockIdx.y, bb = blockIdx.z;
    const int tid = threadIdx.x, warp = tid >> 5, lane = tid & 31;
    const int g = lane >> 2, tc = lane & 3;
    const int wq = warp * 16;

    const size_t base = ((size_t)bb*SEQ)*EMB + (size_t)hh*HEADD;

    #pragma unroll
    for (int i = 0; i < 8; i++) {
        int f   = i*256 + tid;
        int row = f >> 4, d4 = (f & 15) << 2;
        *(uint4*)&qs[row*QS_STRIDE + d4] =
            *(const uint4*)&Q[base + (size_t)(bq*128 + row)*EMB + d4];
    }
    __syncthreads();

    uint32_t qf[8][4];
    #pragma unroll
    for (int ki = 0; ki < 8; ki++) {
        int k0 = ki*8;
        qf[ki][0] = qs[(wq+g  )*QS_STRIDE + k0 + tc];
        qf[ki][1] = qs[(wq+g+8)*QS_STRIDE + k0 + tc];
        qf[ki][2] = qs[(wq+g  )*QS_STRIDE + k0 + tc + 4];
        qf[ki][3] = qs[(wq+g+8)*QS_STRIDE + k0 + tc + 4];
    }

    float o[8][4];
    #pragma unroll
    for (int nt = 0; nt < 8; nt++)
        #pragma unroll
        for (int j = 0; j < 4; j++) o[nt][j] = 0.f;
    float m0 = -1e30f, m1 = -1e30f, l0 = 0.f, l1 = 0.f;

    const int nkt = 2*bq + 2;
    for (int kt = 0; kt < nkt; kt++) {
        __syncthreads();

        #pragma unroll
        for (int i = 0; i < 4; i++) {
            int f   = i*256 + tid;
            int tok = f >> 4, d4 = (f & 15) << 2;
            *(uint4*)&ks[tok*KS_STRIDE + d4] =
                *(const uint4*)&K[base + (size_t)(kt*64 + tok)*EMB + d4];
            *(uint4*)&vs[tok*VS_STRIDE + d4] =
                *(const uint4*)&V[base + (size_t)(kt*64 + tok)*EMB + d4];
        }
        __syncthreads();

        float sc[8][4];
        #pragma unroll
        for (int nt = 0; nt < 8; nt++)
            #pragma unroll
            for (int j = 0; j < 4; j++) sc[nt][j] = 0.f;

        #pragma unroll
        for (int ki = 0; ki < 8; ki++) {
            int k0 = ki*8;
            uint32_t bf[8][2];
            #pragma unroll
            for (int nt = 0; nt < 8; nt++) {
                int nb = nt*8 + g;
                bf[nt][0] = ks[nb*KS_STRIDE + k0 + tc];
                bf[nt][1] = ks[nb*KS_STRIDE + k0 + tc + 4];
            }
            #pragma unroll
            for (int nt = 0; nt < 8; nt++)
                mma_tf32(sc[nt], qf[ki], bf[nt]);
        }

        if (kt >= 2*bq) {
            const int row0 = bq*128 + wq + g;
            #pragma unroll
            for (int nt = 0; nt < 8; nt++) {
                int c0 = kt*64 + nt*8 + 2*tc;
                if (c0     > row0    ) sc[nt][0] = -1e30f;
                if (c0 + 1 > row0    ) sc[nt][1] = -1e30f;
                if (c0     > row0 + 8) sc[nt][2] = -1e30f;
                if (c0 + 1 > row0 + 8) sc[nt][3] = -1e30f;
            }
        }

        float r0 = -1e30f, r1 = -1e30f;
        #pragma unroll
        for (int nt = 0; nt < 8; nt++) {
            r0 = fmaxf(r0, fmaxf(sc[nt][0], sc[nt][1]));
            r1 = fmaxf(r1, fmaxf(sc[nt][2], sc[nt][3]));
        }
        r0 = fmaxf(r0, __shfl_xor_sync(0xffffffffu, r0, 1));
        r0 = fmaxf(r0, __shfl_xor_sync(0xffffffffu, r0, 2));
        r1 = fmaxf(r1, __shfl_xor_sync(0xffffffffu, r1, 1));
        r1 = fmaxf(r1, __shfl_xor_sync(0xffffffffu, r1, 2));

        float mn0 = fmaxf(m0, r0), mn1 = fmaxf(m1, r1);
        float cor0 = __expf(m0 - mn0), cor1 = __expf(m1 - mn1);
        m0 = mn0; m1 = mn1;
        l0 *= cor0; l1 *= cor1;
        #pragma unroll
        for (int nt = 0; nt < 8; nt++) {
            o[nt][0] *= cor0; o[nt][1] *= cor0;
            o[nt][2] *= cor1; o[nt][3] *= cor1;
        }

        float s0 = 0.f, s1 = 0.f;
        #pragma unroll
        for (int nt = 0; nt < 8; nt++) {
            float p00 = __expf(sc[nt][0] - mn0);
            float p01 = __expf(sc[nt][1] - mn0);
            float p10 = __expf(sc[nt][2] - mn1);
            float p11 = __expf(sc[nt][3] - mn1);
            s0 += p00 + p01; s1 += p10 + p11;
            int col = nt*8 + 2*tc;
            ps[(wq+g  )*PS_STRIDE + col    ] = f2tf(p00);
            ps[(wq+g  )*PS_STRIDE + col + 1] = f2tf(p01);
            ps[(wq+g+8)*PS_STRIDE + col    ] = f2tf(p10);
            ps[(wq+g+8)*PS_STRIDE + col + 1] = f2tf(p11);
        }
        s0 += __shfl_xor_sync(0xffffffffu, s0, 1);
        s0 += __shfl_xor_sync(0xffffffffu, s0, 2);
        s1 += __shfl_xor_sync(0xffffffffu, s1, 1);
        s1 += __shfl_xor_sync(0xffffffffu, s1, 2);
        l0 += s0; l1 += s1;
        __syncwarp();

        #pragma unroll
        for (int ki = 0; ki < 8; ki++) {
            int k0 = ki*8;
            uint32_t af[4];
            af[0] = ps[(wq+g  )*PS_STRIDE + k0 + tc];
            af[1] = ps[(wq+g+8)*PS_STRIDE + k0 + tc];
            af[2] = ps[(wq+g  )*PS_STRIDE + k0 + tc + 4];
            af[3] = ps[(wq+g+8)*PS_STRIDE + k0 + tc + 4];
            uint32_t bf[8][2];
            #pragma unroll
            for (int nt = 0; nt < 8; nt++) {
                int nb = nt*8 + g;
                bf[nt][0] = vs[(k0 + tc    )*VS_STRIDE + nb];
                bf[nt][1] = vs[(k0 + tc + 4)*VS_STRIDE + nb];
            }
            #pragma unroll
            for (int nt = 0; nt < 8; nt++)
                mma_tf32(o[nt], af, bf[nt]);
        }
        __syncwarp();
    }

    float inv0 = 1.0f / l0, inv1 = 1.0f / l1;
    const int row0 = bq*128 + wq + g;
    #pragma unroll
    for (int nt = 0; nt < 8; nt++) {
        int d = nt*8 + 2*tc;
        uint2 a = { f2tf(o[nt][0]*inv0), f2tf(o[nt][1]*inv0) };
        *(uint2*)&O[base + (size_t)row0*EMB + d] = a;
        uint2 b = { f2tf(o[nt][2]*inv1), f2tf(o[nt][3]*inv1) };
        *(uint2*)&O[base + (size_t)(row0+8)*EMB + d] = b;
    }
}

// ---------------- orchestration ----------------
extern "C" void kernel_launch(void* const* d_in, const int* in_sizes, int n_in,
                              void* d_out, int out_size)
{
    (void)in_sizes; (void)n_in;
    const int*   x       = (const int*)  d_in[0];
    const float* tok_emb = (const float*)d_in[1];
    const float* pos_emb = (const float*)d_in[2];
    const float* Wq   = (const float*)d_in[3];
    const float* bq   = (const float*)d_in[4];
    const float* Wk   = (const float*)d_in[5];
    const float* bk   = (const float*)d_in[6];
    const float* Wv   = (const float*)d_in[7];
    const float* bv   = (const float*)d_in[8];
    const float* Wo   = (const float*)d_in[9];
    const float* bo   = (const float*)d_in[10];
    const float* ln1s = (const float*)d_in[11];
    const float* ln1b = (const float*)d_in[12];
    const float* ln2s = (const float*)d_in[13];
    const float* ln2b = (const float*)d_in[14];
    const float* W1   = (const float*)d_in[15];
    const float* b1   = (const float*)d_in[16];
    const float* W2   = (const float*)d_in[17];
    const float* b2   = (const float*)d_in[18];
    const float* Wout = (const float*)d_in[19];
    const float* bout = (const float*)d_in[20];
    float* out = (float*)d_out;
    (void)out_size;

    float *h; uint32_t *y, *q, *k, *v, *o, *ff, *htf, *wtf;
    cudaGetSymbolAddress((void**)&h,   g_h);
    cudaGetSymbolAddress((void**)&y,   g_y);
    cudaGetSymbolAddress((void**)&q,   g_q);
    cudaGetSymbolAddress((void**)&k,   g_k);
    cudaGetSymbolAddress((void**)&v,   g_v);
    cudaGetSymbolAddress((void**)&o,   g_o);
    cudaGetSymbolAddress((void**)&ff,  g_ff);
    cudaGetSymbolAddress((void**)&htf, g_htf);
    cudaGetSymbolAddress((void**)&wtf, g_wtf);

    cudaFuncSetAttribute(gemm128<false,false,0>,
        cudaFuncAttributeMaxDynamicSharedMemorySize, GEMM_SMEM_BYTES);
    cudaFuncSetAttribute(gemm128<false,true,0>,
        cudaFuncAttributeMaxDynamicSharedMemorySize, GEMM_SMEM_BYTES);
    cudaFuncSetAttribute(gemm128<false,true,2>,
        cudaFuncAttributeMaxDynamicSharedMemorySize, GEMM_SMEM_BYTES);
    cudaFuncSetAttribute(gemm128<true,false,1>,
        cudaFuncAttributeMaxDynamicSharedMemorySize, GEMM_SMEM_BYTES);
    cudaFuncSetAttribute(qkv_gemm,
        cudaFuncAttributeMaxDynamicSharedMemorySize, GEMM_SMEM_BYTES);
    cudaFuncSetAttribute(attn_mma_kernel,
        cudaFuncAttributeMaxDynamicSharedMemorySize, ATT_SMEM_BYTES);

    // ---- one-time weight conversion to tf32 (inside graph; deterministic) ----
    {
        const int T = 256;
        cvt_tf_kernel<<<EE6/(4*T), T>>>(Wq,   wtf + OFF_WQ,   EE6);
        cvt_tf_kernel<<<EE6/(4*T), T>>>(Wk,   wtf + OFF_WK,   EE6);
        cvt_tf_kernel<<<EE6/(4*T), T>>>(Wv,   wtf + OFF_WV,   EE6);
        cvt_tf_kernel<<<EE6/(4*T), T>>>(Wo,   wtf + OFF_WO,   EE6);
        cvt_tf_kernel<<<EF6/(4*T), T>>>(W1,   wtf + OFF_W1,   EF6);
        cvt_tf_kernel<<<EF6/(4*T), T>>>(W2,   wtf + OFF_W2,   EF6);
        cvt_tf_kernel<<<(EMB*VOCAB)/(4*T), T>>>(Wout, wtf + OFF_WOUT, EMB*VOCAB);
    }

    const int M = BT;
    embed_kernel<<<BT, 128>>>(x, tok_emb, pos_emb, h);

    for (int i = 0; i < NLAYER; i++) {
        const uint32_t* Wqi = wtf + OFF_WQ + (size_t)i*EMB*EMB;
        const uint32_t* Wki = wtf + OFF_WK + (size_t)i*EMB*EMB;
        const uint32_t* Wvi = wtf + OFF_WV + (size_t)i*EMB*EMB;
        const uint32_t* Woi = wtf + OFF_WO + (size_t)i*EMB*EMB;
        const uint32_t* W1i = wtf + OFF_W1 + (size_t)i*EMB*FFDIM;
        const uint32_t* W2i = wtf + OFF_W2 + (size_t)i*FFDIM*EMB;

        ln_kernel<<<BT, 128>>>(h, ln1s + i*EMB, ln1b + i*EMB, y);

        qkv_gemm<<<dim3(12, M/128), 256, GEMM_SMEM_BYTES>>>(
            y, Wqi, Wki, Wvi, bq + i*EMB, bk + i*EMB, bv + i*EMB, q, k, v);

        attn_mma_kernel<<<dim3(SEQ/128, NHEAD, BATCH), 256, ATT_SMEM_BYTES>>>(q, k, v, o);

        gemm128<false,true,0><<<dim3(EMB/128, M/128), 256, GEMM_SMEM_BYTES>>>(
            M, EMB, EMB, o, Woi, bo + i*EMB, h, nullptr);

        ln_kernel<<<BT, 128>>>(h, ln2s + i*EMB, ln2b + i*EMB, y);

        gemm128<true,false,1><<<dim3(FFDIM/128, M/128), 256, GEMM_SMEM_BYTES>>>(
            M, FFDIM, EMB, y, W1i, b1 + i*FFDIM, nullptr, ff);

        if (i < NLAYER - 1) {
            gemm128<false,true,0><<<dim3(EMB/128, M/128), 256, GEMM_SMEM_BYTES>>>(
                M, EMB, FFDIM, ff, W2i, b2 + i*EMB, h, nullptr);
        } else {
            gemm128<false,true,2><<<dim3(EMB/128, M/128), 256, GEMM_SMEM_BYTES>>>(
                M, EMB, FFDIM, ff, W2i, b2 + i*EMB, h, htf);
        }
    }

    gemm128<false,false,0><<<dim3(VOCAB/128, M/128), 256, GEMM_SMEM_BYTES>>>(
        M, VOCAB, EMB, htf, wtf + OFF_WOUT, bout, out, nullptr);
}

// round 9
// speedup vs baseline: 1.3492x; 1.0880x over previous
#include <cuda_runtime.h>
#include <cuda_bf16.h>
#include <math.h>
#include <stdint.h>

// ---------------- problem constants ----------------
#define VOCAB 32000
#define EMB   512
#define SEQ   2048
#define NHEAD 8
#define NLAYER 6
#define FFDIM 2048
#define BATCH 2
#define HEADD 64
#define BT    (BATCH*SEQ)      // 4096 tokens
#define EPS_LN 1e-5f

// ---------------- scratch (device globals; no allocation allowed) ----------------
__device__ float    g_h  [BT*EMB];     // residual stream (fp32)
__device__ uint32_t g_y  [BT*EMB];     // LN output (tf32)
__device__ uint32_t g_q  [BT*EMB];     // tf32, pre-scaled by 0.125
__device__ uint32_t g_k  [BT*EMB];     // tf32
__device__ uint32_t g_v  [BT*EMB];     // tf32
__device__ uint32_t g_o  [BT*EMB];     // attention output (tf32)
__device__ uint32_t g_ff [BT*FFDIM];   // FFN hidden (tf32)
__device__ uint32_t g_htf[BT*EMB];     // final residual (tf32) for vocab gemm

// tf32 weight mirror, same [K][N] layout as inputs
#define EE6 (NLAYER*EMB*EMB)
#define EF6 (NLAYER*EMB*FFDIM)
#define OFF_WQ   0
#define OFF_WK   (EE6)
#define OFF_WV   (2*EE6)
#define OFF_WO   (3*EE6)
#define OFF_W1   (4*EE6)
#define OFF_W2   (4*EE6 + EF6)
#define OFF_WOUT (4*EE6 + 2*EF6)
#define WTF_TOTAL (4*EE6 + 2*EF6 + EMB*VOCAB)
__device__ uint32_t g_wtf[WTF_TOTAL];

// ---------------- helpers ----------------
__device__ __forceinline__ uint32_t f2tf(float f) {
    uint32_t u; asm("cvt.rna.tf32.f32 %0, %1;" : "=r"(u) : "f"(f)); return u;
}
__device__ __forceinline__ void mma_tf32(float* c, const uint32_t* a, const uint32_t* b) {
    asm volatile(
        "mma.sync.aligned.m16n8k8.row.col.f32.tf32.tf32.f32 "
        "{%0,%1,%2,%3}, {%4,%5,%6,%7}, {%8,%9}, {%0,%1,%2,%3};\n"
        : "+f"(c[0]), "+f"(c[1]), "+f"(c[2]), "+f"(c[3])
        : "r"(a[0]), "r"(a[1]), "r"(a[2]), "r"(a[3]),
          "r"(b[0]), "r"(b[1]));
}
__device__ __forceinline__ uint32_t smem_u32(const void* p) {
    uint32_t a;
    asm("{ .reg .u64 t; cvta.to.shared.u64 t, %1; cvt.u32.u64 %0, t; }" : "=r"(a) : "l"(p));
    return a;
}
#define CP_ASYNC16(dst, src) \
    asm volatile("cp.async.cg.shared.global [%0], [%1], 16;" :: "r"(dst), "l"(src))
#define CP_COMMIT() asm volatile("cp.async.commit_group;" ::: "memory")
#define CP_WAIT1()  asm volatile("cp.async.wait_group 1;" ::: "memory")

// ---------------- one-time weight convert fp32 -> tf32 ----------------
__global__ void cvt_tf_kernel(const float* __restrict__ s, uint32_t* __restrict__ d, int n)
{
    int i = (blockIdx.x * 256 + threadIdx.x) * 4;
    if (i < n) {
        float4 v = *(const float4*)&s[i];
        uint4 u = { f2tf(v.x), f2tf(v.y), f2tf(v.z), f2tf(v.w) };
        *(uint4*)&d[i] = u;
    }
}

// ---------------- embedding ----------------
__global__ void embed_kernel(const int* __restrict__ x,
                             const float* __restrict__ tok,
                             const float* __restrict__ pos,
                             float* __restrict__ h)
{
    int row = blockIdx.x;
    int t   = row % SEQ;
    int id  = x[row];
    const float* te = tok + (size_t)id * EMB;
    const float* pe = pos + (size_t)t  * EMB;
    float* out = h + (size_t)row * EMB;
    for (int i = threadIdx.x; i < EMB; i += blockDim.x)
        out[i] = te[i] + pe[i];
}

// ---------------- layernorm (emits tf32 directly) ----------------
__global__ void ln_kernel(const float* __restrict__ X,
                          const float* __restrict__ scale,
                          const float* __restrict__ bias,
                          uint32_t* __restrict__ Y)
{
    int row = blockIdx.x;
    int t = threadIdx.x;                   // 128 threads
    const float* x = X + (size_t)row * EMB;
    uint32_t* y = Y + (size_t)row * EMB;

    float s = 0.f, sq = 0.f;
    #pragma unroll
    for (int i = t; i < EMB; i += 128) { float v = x[i]; s += v; sq += v*v; }

    __shared__ float r1[128], r2[128];
    r1[t] = s; r2[t] = sq;
    __syncthreads();
    for (int k = 64; k > 0; k >>= 1) {
        if (t < k) { r1[t] += r1[t+k]; r2[t] += r2[t+k]; }
        __syncthreads();
    }
    float mean = r1[0] * (1.0f/EMB);
    float var  = r2[0] * (1.0f/EMB) - mean*mean;
    float rstd = rsqrtf(var + EPS_LN);

    #pragma unroll
    for (int i = t; i < EMB; i += 128)
        y[i] = f2tf((x[i] - mean) * rstd * scale[i] + bias[i]);
}

// ---------------- tf32 GEMM with cp.async 3-stage pipeline ----------------
// Block tile 128x128x32, 256 threads = 8 warps (2 along M x 4 along N),
// warp tile 64x32 = 4x4 m16n8k8 tiles. 3-stage cp.async ring; 2 CTAs/SM.
// TFM: 0 = fp32 C only, 1 = tf32 Ctf only, 2 = both.
#define APAD 36    // A row stride (words)
#define WPAD 136   // W row stride (words)
#define STG_WORDS (128*APAD + 32*WPAD)         // 8960 words / stage
#define NSTAGE 3
#define GEMM_SMEM_BYTES (NSTAGE*STG_WORDS*4)   // 107520 B

template<bool RELU, bool RES, int TFM>
__device__ __forceinline__ void gemm_core(
    const uint32_t* __restrict__ A,
    const uint32_t* __restrict__ W,
    const float* __restrict__ bias,
    float* __restrict__ C,
    uint32_t* __restrict__ Ctf,
    float tfscale,
    int M, int N, int K, int bx, int by, uint32_t* dsm)
{
    const int tid  = threadIdx.x;
    const int warp = tid >> 5, lane = tid & 31;
    const int m0   = (warp & 1) * 64;
    const int n0   = (warp >> 1) * 32;
    const int group = lane >> 2, tcol = lane & 3;

    const int aRow = tid >> 3;
    const int aCol = (tid & 7) << 2;
    const int wRow = tid >> 3;
    const int wCol = (tid & 7) << 2;

    const uint32_t smb = smem_u32(dsm);

    // per-thread gmem/smem staging bases
    const uint32_t aDst = smb + (uint32_t)(aRow*APAD + aCol)*4;
    const uint32_t wDst = smb + (uint32_t)(128*APAD + wRow*WPAD + wCol)*4;

    float c[4][4][4];
    #pragma unroll
    for (int mt = 0; mt < 4; mt++)
        #pragma unroll
        for (int nt = 0; nt < 4; nt++)
            #pragma unroll
            for (int j = 0; j < 4; j++) c[mt][nt][j] = 0.f;

    const int ktiles = K >> 5;

    // ---- issue stage for k-tile kt into ring slot kt%NSTAGE ----
    #define ISSUE_STAGE(kt_) do {                                              \
        const int _kb = (kt_) << 5;                                            \
        const uint32_t _so = (uint32_t)(((kt_) % NSTAGE) * STG_WORDS * 4);     \
        _Pragma("unroll")                                                      \
        for (int i = 0; i < 4; i++)                                            \
            CP_ASYNC16(aDst + _so + (uint32_t)(i*32*APAD)*4,                   \
                       &A[(size_t)(by*128 + aRow + i*32)*K + _kb + aCol]);     \
        _Pragma("unroll")                                                      \
        for (int i = 0; i < 4; i++)                                            \
            CP_ASYNC16(wDst + _so + (uint32_t)(i*32)*4,                        \
                       &W[(size_t)(_kb + wRow)*N + bx*128 + wCol + i*32]);     \
    } while (0)

    // prologue: stages 0 and 1 (ktiles >= 2 always)
    ISSUE_STAGE(0); CP_COMMIT();
    ISSUE_STAGE(1); CP_COMMIT();

    for (int kt = 0; kt < ktiles; kt++) {
        CP_WAIT1();          // groups 0..kt complete
        __syncthreads();

        const uint32_t* Ass = dsm + (kt % NSTAGE)*STG_WORDS;
        const uint32_t* Wss = Ass + 128*APAD;

        #pragma unroll
        for (int ks = 0; ks < 4; ks++) {
            const int k0 = ks << 3;
            uint32_t af[4][4], bf[4][2];
            #pragma unroll
            for (int mt = 0; mt < 4; mt++) {
                const int mb = m0 + mt*16 + group;
                af[mt][0] = Ass[(mb    )*APAD + k0 + tcol];
                af[mt][1] = Ass[(mb + 8)*APAD + k0 + tcol];
                af[mt][2] = Ass[(mb    )*APAD + k0 + tcol + 4];
                af[mt][3] = Ass[(mb + 8)*APAD + k0 + tcol + 4];
            }
            #pragma unroll
            for (int nt = 0; nt < 4; nt++) {
                const int nb = n0 + nt*8 + group;
                bf[nt][0] = Wss[(k0 + tcol    )*WPAD + nb];
                bf[nt][1] = Wss[(k0 + tcol + 4)*WPAD + nb];
            }
            #pragma unroll
            for (int mt = 0; mt < 4; mt++)
                #pragma unroll
                for (int nt = 0; nt < 4; nt++)
                    mma_tf32(c[mt][nt], af[mt], bf[nt]);
        }

        __syncthreads();     // all warps done with slot (kt+2)%NSTAGE's previous contents
        if (kt + 2 < ktiles) ISSUE_STAGE(kt + 2);
        CP_COMMIT();         // commit every iter (possibly empty) to keep accounting
    }
    #undef ISSUE_STAGE

    // ---- epilogue ----
    #pragma unroll
    for (int mt = 0; mt < 4; mt++) {
        #pragma unroll
        for (int nt = 0; nt < 4; nt++) {
            const int col = bx*128 + n0 + nt*8 + tcol*2;
            float2 bb = *(const float2*)&bias[col];
            #pragma unroll
            for (int r = 0; r < 2; r++) {
                const int row = by*128 + m0 + mt*16 + group + r*8;
                float2 v;
                v.x = c[mt][nt][r*2+0] + bb.x;
                v.y = c[mt][nt][r*2+1] + bb.y;
                if (RELU) { v.x = fmaxf(v.x, 0.f); v.y = fmaxf(v.y, 0.f); }
                float2* cp = (float2*)&C[(size_t)row*N + col];
                if (RES) { float2 o = *cp; v.x += o.x; v.y += o.y; }
                if (TFM != 1) *cp = v;
                if (TFM >= 1) {
                    uint2 t2 = { f2tf(v.x * tfscale), f2tf(v.y * tfscale) };
                    *(uint2*)&Ctf[(size_t)row*N + col] = t2;
                }
            }
        }
    }
}

template<bool RELU, bool RES, int TFM>
__global__ __launch_bounds__(256, 2) void gemm128(
    int M, int N, int K,
    const uint32_t* __restrict__ A,
    const uint32_t* __restrict__ W,
    const float* __restrict__ bias,
    float* __restrict__ C,
    uint32_t* __restrict__ Ctf)
{
    extern __shared__ uint32_t dsm[];
    gemm_core<RELU,RES,TFM>(A, W, bias, C, Ctf, 1.0f, M, N, K, blockIdx.x, blockIdx.y, dsm);
}

// fused QKV: grid.x = 12 (3 weights x 4 N-tiles); outputs tf32 only, q pre-scaled.
__global__ __launch_bounds__(256, 2) void qkv_gemm(
    const uint32_t* __restrict__ A,
    const uint32_t* __restrict__ Wq, const uint32_t* __restrict__ Wk, const uint32_t* __restrict__ Wv,
    const float* __restrict__ bq, const float* __restrict__ bk, const float* __restrict__ bv,
    uint32_t* __restrict__ q, uint32_t* __restrict__ k, uint32_t* __restrict__ v)
{
    extern __shared__ uint32_t dsm[];
    const int w   = blockIdx.x >> 2;
    const int nbx = blockIdx.x & 3;
    const uint32_t* W = (w == 0) ? Wq : (w == 1) ? Wk : Wv;
    const float*    b = (w == 0) ? bq : (w == 1) ? bk : bv;
    uint32_t*       C = (w == 0) ? q  : (w == 1) ? k  : v;
    const float    sc = (w == 0) ? 0.125f : 1.0f;
    gemm_core<false,false,1>(A, W, b, nullptr, C, sc, BT, EMB, EMB, nbx, blockIdx.y, dsm);
}

// ---------------- tensor-core flash attention (tf32 in/out; unchanged) ----------------
#define QS_STRIDE 68
#define KS_STRIDE 68
#define VS_STRIDE 72
#define PS_STRIDE 68
#define ATT_SMEM_WORDS (128*QS_STRIDE + 64*KS_STRIDE + 64*VS_STRIDE)
#define ATT_SMEM_BYTES (ATT_SMEM_WORDS*4)

__global__ __launch_bounds__(256, 2) void attn_mma_kernel(
        const uint32_t* __restrict__ Q,
        const uint32_t* __restrict__ K,
        const uint32_t* __restrict__ V,
        uint32_t* __restrict__ O)
{
    extern __shared__ uint32_t smw[];
    uint32_t* qs = smw;
    uint32_t* ks = qs + 128*QS_STRIDE;
    uint32_t* vs = ks + 64*KS_STRIDE;
    uint32_t* ps = qs;

    const int bq = blockIdx.x, hh = blockIdx.y, bb = blockIdx.z;
    const int tid = threadIdx.x, warp = tid >> 5, lane = tid & 31;
    const int g = lane >> 2, tc = lane & 3;
    const int wq = warp * 16;

    const size_t base = ((size_t)bb*SEQ)*EMB + (size_t)hh*HEADD;

    #pragma unroll
    for (int i = 0; i < 8; i++) {
        int f   = i*256 + tid;
        int row = f >> 4, d4 = (f & 15) << 2;
        *(uint4*)&qs[row*QS_STRIDE + d4] =
            *(const uint4*)&Q[base + (size_t)(bq*128 + row)*EMB + d4];
    }
    __syncthreads();

    uint32_t qf[8][4];
    #pragma unroll
    for (int ki = 0; ki < 8; ki++) {
        int k0 = ki*8;
        qf[ki][0] = qs[(wq+g  )*QS_STRIDE + k0 + tc];
        qf[ki][1] = qs[(wq+g+8)*QS_STRIDE + k0 + tc];
        qf[ki][2] = qs[(wq+g  )*QS_STRIDE + k0 + tc + 4];
        qf[ki][3] = qs[(wq+g+8)*QS_STRIDE + k0 + tc + 4];
    }

    float o[8][4];
    #pragma unroll
    for (int nt = 0; nt < 8; nt++)
        #pragma unroll
        for (int j = 0; j < 4; j++) o[nt][j] = 0.f;
    float m0 = -1e30f, m1 = -1e30f, l0 = 0.f, l1 = 0.f;

    const int nkt = 2*bq + 2;
    for (int kt = 0; kt < nkt; kt++) {
        __syncthreads();

        #pragma unroll
        for (int i = 0; i < 4; i++) {
            int f   = i*256 + tid;
            int tok = f >> 4, d4 = (f & 15) << 2;
            *(uint4*)&ks[tok*KS_STRIDE + d4] =
                *(const uint4*)&K[base + (size_t)(kt*64 + tok)*EMB + d4];
            *(uint4*)&vs[tok*VS_STRIDE + d4] =
                *(const uint4*)&V[base + (size_t)(kt*64 + tok)*EMB + d4];
        }
        __syncthreads();

        float sc[8][4];
        #pragma unroll
        for (int nt = 0; nt < 8; nt++)
            #pragma unroll
            for (int j = 0; j < 4; j++) sc[nt][j] = 0.f;

        #pragma unroll
        for (int ki = 0; ki < 8; ki++) {
            int k0 = ki*8;
            uint32_t bf[8][2];
            #pragma unroll
            for (int nt = 0; nt < 8; nt++) {
                int nb = nt*8 + g;
                bf[nt][0] = ks[nb*KS_STRIDE + k0 + tc];
                bf[nt][1] = ks[nb*KS_STRIDE + k0 + tc + 4];
            }
            #pragma unroll
            for (int nt = 0; nt < 8; nt++)
                mma_tf32(sc[nt], qf[ki], bf[nt]);
        }

        if (kt >= 2*bq) {
            const int row0 = bq*128 + wq + g;
            #pragma unroll
            for (int nt = 0; nt < 8; nt++) {
                int c0 = kt*64 + nt*8 + 2*tc;
                if (c0     > row0    ) sc[nt][0] = -1e30f;
                if (c0 + 1 > row0    ) sc[nt][1] = -1e30f;
                if (c0     > row0 + 8) sc[nt][2] = -1e30f;
                if (c0 + 1 > row0 + 8) sc[nt][3] = -1e30f;
            }
        }

        float r0 = -1e30f, r1 = -1e30f;
        #pragma unroll
        for (int nt = 0; nt < 8; nt++) {
            r0 = fmaxf(r0, fmaxf(sc[nt][0], sc[nt][1]));
            r1 = fmaxf(r1, fmaxf(sc[nt][2], sc[nt][3]));
        }
        r0 = fmaxf(r0, __shfl_xor_sync(0xffffffffu, r0, 1));
        r0 = fmaxf(r0, __shfl_xor_sync(0xffffffffu, r0, 2));
        r1 = fmaxf(r1, __shfl_xor_sync(0xffffffffu, r1, 1));
        r1 = fmaxf(r1, __shfl_xor_sync(0xffffffffu, r1, 2));

        float mn0 = fmaxf(m0, r0), mn1 = fmaxf(m1, r1);
        float cor0 = __expf(m0 - mn0), cor1 = __expf(m1 - mn1);
        m0 = mn0; m1 = mn1;
        l0 *= cor0; l1 *= cor1;
        #pragma unroll
        for (int nt = 0; nt < 8; nt++) {
            o[nt][0] *= cor0; o[nt][1] *= cor0;
            o[nt][2] *= cor1; o[nt][3] *= cor1;
        }

        float s0 = 0.f, s1 = 0.f;
        #pragma unroll
        for (int nt = 0; nt < 8; nt++) {
            float p00 = __expf(sc[nt][0] - mn0);
            float p01 = __expf(sc[nt][1] - mn0);
            float p10 = __expf(sc[nt][2] - mn1);
            float p11 = __expf(sc[nt][3] - mn1);
            s0 += p00 + p01; s1 += p10 + p11;
            int col = nt*8 + 2*tc;
            ps[(wq+g  )*PS_STRIDE + col    ] = f2tf(p00);
            ps[(wq+g  )*PS_STRIDE + col + 1] = f2tf(p01);
            ps[(wq+g+8)*PS_STRIDE + col    ] = f2tf(p10);
            ps[(wq+g+8)*PS_STRIDE + col + 1] = f2tf(p11);
        }
        s0 += __shfl_xor_sync(0xffffffffu, s0, 1);
        s0 += __shfl_xor_sync(0xffffffffu, s0, 2);
        s1 += __shfl_xor_sync(0xffffffffu, s1, 1);
        s1 += __shfl_xor_sync(0xffffffffu, s1, 2);
        l0 += s0; l1 += s1;
        __syncwarp();

        #pragma unroll
        for (int ki = 0; ki < 8; ki++) {
            int k0 = ki*8;
            uint32_t af[4];
            af[0] = ps[(wq+g  )*PS_STRIDE + k0 + tc];
            af[1] = ps[(wq+g+8)*PS_STRIDE + k0 + tc];
            af[2] = ps[(wq+g  )*PS_STRIDE + k0 + tc + 4];
            af[3] = ps[(wq+g+8)*PS_STRIDE + k0 + tc + 4];
            uint32_t bf[8][2];
            #pragma unroll
            for (int nt = 0; nt < 8; nt++) {
                int nb = nt*8 + g;
                bf[nt][0] = vs[(k0 + tc    )*VS_STRIDE + nb];
                bf[nt][1] = vs[(k0 + tc + 4)*VS_STRIDE + nb];
            }
            #pragma unroll
            for (int nt = 0; nt < 8; nt++)
                mma_tf32(o[nt], af, bf[nt]);
        }
        __syncwarp();
    }

    float inv0 = 1.0f / l0, inv1 = 1.0f / l1;
    const int row0 = bq*128 + wq + g;
    #pragma unroll
    for (int nt = 0; nt < 8; nt++) {
        int d = nt*8 + 2*tc;
        uint2 a = { f2tf(o[nt][0]*inv0), f2tf(o[nt][1]*inv0) };
        *(uint2*)&O[base + (size_t)row0*EMB + d] = a;
        uint2 b = { f2tf(o[nt][2]*inv1), f2tf(o[nt][3]*inv1) };
        *(uint2*)&O[base + (size_t)(row0+8)*EMB + d] = b;
    }
}

// ---------------- orchestration ----------------
extern "C" void kernel_launch(void* const* d_in, const int* in_sizes, int n_in,
                              void* d_out, int out_size)
{
    (void)in_sizes; (void)n_in;
    const int*   x       = (const int*)  d_in[0];
    const float* tok_emb = (const float*)d_in[1];
    const float* pos_emb = (const float*)d_in[2];
    const float* Wq   = (const float*)d_in[3];
    const float* bq   = (const float*)d_in[4];
    const float* Wk   = (const float*)d_in[5];
    const float* bk   = (const float*)d_in[6];
    const float* Wv   = (const float*)d_in[7];
    const float* bv   = (const float*)d_in[8];
    const float* Wo   = (const float*)d_in[9];
    const float* bo   = (const float*)d_in[10];
    const float* ln1s = (const float*)d_in[11];
    const float* ln1b = (const float*)d_in[12];
    const float* ln2s = (const float*)d_in[13];
    const float* ln2b = (const float*)d_in[14];
    const float* W1   = (const float*)d_in[15];
    const float* b1   = (const float*)d_in[16];
    const float* W2   = (const float*)d_in[17];
    const float* b2   = (const float*)d_in[18];
    const float* Wout = (const float*)d_in[19];
    const float* bout = (const float*)d_in[20];
    float* out = (float*)d_out;
    (void)out_size;

    float *h; uint32_t *y, *q, *k, *v, *o, *ff, *htf, *wtf;
    cudaGetSymbolAddress((void**)&h,   g_h);
    cudaGetSymbolAddress((void**)&y,   g_y);
    cudaGetSymbolAddress((void**)&q,   g_q);
    cudaGetSymbolAddress((void**)&k,   g_k);
    cudaGetSymbolAddress((void**)&v,   g_v);
    cudaGetSymbolAddress((void**)&o,   g_o);
    cudaGetSymbolAddress((void**)&ff,  g_ff);
    cudaGetSymbolAddress((void**)&htf, g_htf);
    cudaGetSymbolAddress((void**)&wtf, g_wtf);

    cudaFuncSetAttribute(gemm128<false,false,0>,
        cudaFuncAttributeMaxDynamicSharedMemorySize, GEMM_SMEM_BYTES);
    cudaFuncSetAttribute(gemm128<false,true,0>,
        cudaFuncAttributeMaxDynamicSharedMemorySize, GEMM_SMEM_BYTES);
    cudaFuncSetAttribute(gemm128<false,true,2>,
        cudaFuncAttributeMaxDynamicSharedMemorySize, GEMM_SMEM_BYTES);
    cudaFuncSetAttribute(gemm128<true,false,1>,
        cudaFuncAttributeMaxDynamicSharedMemorySize, GEMM_SMEM_BYTES);
    cudaFuncSetAttribute(qkv_gemm,
        cudaFuncAttributeMaxDynamicSharedMemorySize, GEMM_SMEM_BYTES);
    cudaFuncSetAttribute(attn_mma_kernel,
        cudaFuncAttributeMaxDynamicSharedMemorySize, ATT_SMEM_BYTES);

    // ---- one-time weight conversion to tf32 ----
    {
        const int T = 256;
        cvt_tf_kernel<<<EE6/(4*T), T>>>(Wq,   wtf + OFF_WQ,   EE6);
        cvt_tf_kernel<<<EE6/(4*T), T>>>(Wk,   wtf + OFF_WK,   EE6);
        cvt_tf_kernel<<<EE6/(4*T), T>>>(Wv,   wtf + OFF_WV,   EE6);
        cvt_tf_kernel<<<EE6/(4*T), T>>>(Wo,   wtf + OFF_WO,   EE6);
        cvt_tf_kernel<<<EF6/(4*T), T>>>(W1,   wtf + OFF_W1,   EF6);
        cvt_tf_kernel<<<EF6/(4*T), T>>>(W2,   wtf + OFF_W2,   EF6);
        cvt_tf_kernel<<<(EMB*VOCAB)/(4*T), T>>>(Wout, wtf + OFF_WOUT, EMB*VOCAB);
    }

    const int M = BT;
    embed_kernel<<<BT, 128>>>(x, tok_emb, pos_emb, h);

    for (int i = 0; i < NLAYER; i++) {
        const uint32_t* Wqi = wtf + OFF_WQ + (size_t)i*EMB*EMB;
        const uint32_t* Wki = wtf + OFF_WK + (size_t)i*EMB*EMB;
        const uint32_t* Wvi = wtf + OFF_WV + (size_t)i*EMB*EMB;
        const uint32_t* Woi = wtf + OFF_WO + (size_t)i*EMB*EMB;
        const uint32_t* W1i = wtf + OFF_W1 + (size_t)i*EMB*FFDIM;
        const uint32_t* W2i = wtf + OFF_W2 + (size_t)i*FFDIM*EMB;

        ln_kernel<<<BT, 128>>>(h, ln1s + i*EMB, ln1b + i*EMB, y);

        qkv_gemm<<<dim3(12, M/128), 256, GEMM_SMEM_BYTES>>>(
            y, Wqi, Wki, Wvi, bq + i*EMB, bk + i*EMB, bv + i*EMB, q, k, v);

        attn_mma_kernel<<<dim3(SEQ/128, NHEAD, BATCH), 256, ATT_SMEM_BYTES>>>(q, k, v, o);

        gemm128<false,true,0><<<dim3(EMB/128, M/128), 256, GEMM_SMEM_BYTES>>>(
            M, EMB, EMB, o, Woi, bo + i*EMB, h, nullptr);

        ln_kernel<<<BT, 128>>>(h, ln2s + i*EMB, ln2b + i*EMB, y);

        gemm128<true,false,1><<<dim3(FFDIM/128, M/128), 256, GEMM_SMEM_BYTES>>>(
            M, FFDIM, EMB, y, W1i, b1 + i*FFDIM, nullptr, ff);

        if (i < NLAYER - 1) {
            gemm128<false,true,0><<<dim3(EMB/128, M/128), 256, GEMM_SMEM_BYTES>>>(
                M, EMB, FFDIM, ff, W2i, b2 + i*EMB, h, nullptr);
        } else {
            gemm128<false,true,2><<<dim3(EMB/128, M/128), 256, GEMM_SMEM_BYTES>>>(
                M, EMB, FFDIM, ff, W2i, b2 + i*EMB, h, htf);
        }
    }

    gemm128<false,false,0><<<dim3(VOCAB/128, M/128), 256, GEMM_SMEM_BYTES>>>(
        M, VOCAB, EMB, htf, wtf + OFF_WOUT, bout, out, nullptr);
}

// round 10
// speedup vs baseline: 1.3552x; 1.0044x over previous
#include <cuda_runtime.h>
#include <cuda_bf16.h>
#include <math.h>
#include <stdint.h>

// ---------------- problem constants ----------------
#define VOCAB 32000
#define EMB   512
#define SEQ   2048
#define NHEAD 8
#define NLAYER 6
#define FFDIM 2048
#define BATCH 2
#define HEADD 64
#define BT    (BATCH*SEQ)      // 4096 tokens
#define EPS_LN 1e-5f

// ---------------- scratch (device globals; no allocation allowed) ----------------
__device__ float    g_h  [BT*EMB];     // residual stream (fp32)
__device__ uint32_t g_y  [BT*EMB];     // LN output (tf32)
__device__ uint32_t g_q  [BT*EMB];     // tf32, pre-scaled by 0.125
__device__ uint32_t g_k  [BT*EMB];     // tf32
__device__ uint32_t g_v  [BT*EMB];     // tf32
__device__ uint32_t g_o  [BT*EMB];     // attention output (tf32)
__device__ uint32_t g_ff [BT*FFDIM];   // FFN hidden (tf32)
__device__ uint32_t g_htf[BT*EMB];     // final residual (tf32) for vocab gemm

// tf32 weight mirror, same [K][N] layout as inputs
#define EE6 (NLAYER*EMB*EMB)
#define EF6 (NLAYER*EMB*FFDIM)
#define OFF_WQ   0
#define OFF_WK   (EE6)
#define OFF_WV   (2*EE6)
#define OFF_WO   (3*EE6)
#define OFF_W1   (4*EE6)
#define OFF_W2   (4*EE6 + EF6)
#define OFF_WOUT (4*EE6 + 2*EF6)
#define WTF_TOTAL (4*EE6 + 2*EF6 + EMB*VOCAB)
__device__ uint32_t g_wtf[WTF_TOTAL];

// ---------------- helpers ----------------
__device__ __forceinline__ uint32_t f2tf(float f) {
    uint32_t u; asm("cvt.rna.tf32.f32 %0, %1;" : "=r"(u) : "f"(f)); return u;
}
__device__ __forceinline__ void mma_tf32(float* c, const uint32_t* a, const uint32_t* b) {
    asm volatile(
        "mma.sync.aligned.m16n8k8.row.col.f32.tf32.tf32.f32 "
        "{%0,%1,%2,%3}, {%4,%5,%6,%7}, {%8,%9}, {%0,%1,%2,%3};\n"
        : "+f"(c[0]), "+f"(c[1]), "+f"(c[2]), "+f"(c[3])
        : "r"(a[0]), "r"(a[1]), "r"(a[2]), "r"(a[3]),
          "r"(b[0]), "r"(b[1]));
}
__device__ __forceinline__ uint32_t smem_u32(const void* p) {
    uint32_t a;
    asm("{ .reg .u64 t; cvta.to.shared.u64 t, %1; cvt.u32.u64 %0, t; }" : "=r"(a) : "l"(p));
    return a;
}
#define CP_ASYNC16(dst, src) \
    asm volatile("cp.async.cg.shared.global [%0], [%1], 16;" :: "r"(dst), "l"(src))
#define CP_COMMIT() asm volatile("cp.async.commit_group;" ::: "memory")
#define CP_WAIT1()  asm volatile("cp.async.wait_group 1;" ::: "memory")
#define CP_WAIT0()  asm volatile("cp.async.wait_group 0;" ::: "memory")

// ---------------- one-time weight convert fp32 -> tf32 ----------------
__global__ void cvt_tf_kernel(const float* __restrict__ s, uint32_t* __restrict__ d, int n)
{
    int i = (blockIdx.x * 256 + threadIdx.x) * 4;
    if (i < n) {
        float4 v = *(const float4*)&s[i];
        uint4 u = { f2tf(v.x), f2tf(v.y), f2tf(v.z), f2tf(v.w) };
        *(uint4*)&d[i] = u;
    }
}

// ---------------- embedding ----------------
__global__ void embed_kernel(const int* __restrict__ x,
                             const float* __restrict__ tok,
                             const float* __restrict__ pos,
                             float* __restrict__ h)
{
    int row = blockIdx.x;
    int t   = row % SEQ;
    int id  = x[row];
    const float* te = tok + (size_t)id * EMB;
    const float* pe = pos + (size_t)t  * EMB;
    float* out = h + (size_t)row * EMB;
    for (int i = threadIdx.x; i < EMB; i += blockDim.x)
        out[i] = te[i] + pe[i];
}

// ---------------- layernorm (emits tf32 directly) ----------------
__global__ void ln_kernel(const float* __restrict__ X,
                          const float* __restrict__ scale,
                          const float* __restrict__ bias,
                          uint32_t* __restrict__ Y)
{
    int row = blockIdx.x;
    int t = threadIdx.x;                   // 128 threads
    const float* x = X + (size_t)row * EMB;
    uint32_t* y = Y + (size_t)row * EMB;

    float s = 0.f, sq = 0.f;
    #pragma unroll
    for (int i = t; i < EMB; i += 128) { float v = x[i]; s += v; sq += v*v; }

    __shared__ float r1[128], r2[128];
    r1[t] = s; r2[t] = sq;
    __syncthreads();
    for (int k = 64; k > 0; k >>= 1) {
        if (t < k) { r1[t] += r1[t+k]; r2[t] += r2[t+k]; }
        __syncthreads();
    }
    float mean = r1[0] * (1.0f/EMB);
    float var  = r2[0] * (1.0f/EMB) - mean*mean;
    float rstd = rsqrtf(var + EPS_LN);

    #pragma unroll
    for (int i = t; i < EMB; i += 128)
        y[i] = f2tf((x[i] - mean) * rstd * scale[i] + bias[i]);
}

// ---------------- tf32 GEMM with cp.async 3-stage pipeline (unchanged) ----------------
#define APAD 36
#define WPAD 136
#define STG_WORDS (128*APAD + 32*WPAD)
#define NSTAGE 3
#define GEMM_SMEM_BYTES (NSTAGE*STG_WORDS*4)   // 107520 B

template<bool RELU, bool RES, int TFM>
__device__ __forceinline__ void gemm_core(
    const uint32_t* __restrict__ A,
    const uint32_t* __restrict__ W,
    const float* __restrict__ bias,
    float* __restrict__ C,
    uint32_t* __restrict__ Ctf,
    float tfscale,
    int M, int N, int K, int bx, int by, uint32_t* dsm)
{
    const int tid  = threadIdx.x;
    const int warp = tid >> 5, lane = tid & 31;
    const int m0   = (warp & 1) * 64;
    const int n0   = (warp >> 1) * 32;
    const int group = lane >> 2, tcol = lane & 3;

    const int aRow = tid >> 3;
    const int aCol = (tid & 7) << 2;
    const int wRow = tid >> 3;
    const int wCol = (tid & 7) << 2;

    const uint32_t smb = smem_u32(dsm);
    const uint32_t aDst = smb + (uint32_t)(aRow*APAD + aCol)*4;
    const uint32_t wDst = smb + (uint32_t)(128*APAD + wRow*WPAD + wCol)*4;

    float c[4][4][4];
    #pragma unroll
    for (int mt = 0; mt < 4; mt++)
        #pragma unroll
        for (int nt = 0; nt < 4; nt++)
            #pragma unroll
            for (int j = 0; j < 4; j++) c[mt][nt][j] = 0.f;

    const int ktiles = K >> 5;

    #define ISSUE_STAGE(kt_) do {                                              \
        const int _kb = (kt_) << 5;                                            \
        const uint32_t _so = (uint32_t)(((kt_) % NSTAGE) * STG_WORDS * 4);     \
        _Pragma("unroll")                                                      \
        for (int i = 0; i < 4; i++)                                            \
            CP_ASYNC16(aDst + _so + (uint32_t)(i*32*APAD)*4,                   \
                       &A[(size_t)(by*128 + aRow + i*32)*K + _kb + aCol]);     \
        _Pragma("unroll")                                                      \
        for (int i = 0; i < 4; i++)                                            \
            CP_ASYNC16(wDst + _so + (uint32_t)(i*32)*4,                        \
                       &W[(size_t)(_kb + wRow)*N + bx*128 + wCol + i*32]);     \
    } while (0)

    ISSUE_STAGE(0); CP_COMMIT();
    ISSUE_STAGE(1); CP_COMMIT();

    for (int kt = 0; kt < ktiles; kt++) {
        CP_WAIT1();
        __syncthreads();

        const uint32_t* Ass = dsm + (kt % NSTAGE)*STG_WORDS;
        const uint32_t* Wss = Ass + 128*APAD;

        #pragma unroll
        for (int ks = 0; ks < 4; ks++) {
            const int k0 = ks << 3;
            uint32_t af[4][4], bf[4][2];
            #pragma unroll
            for (int mt = 0; mt < 4; mt++) {
                const int mb = m0 + mt*16 + group;
                af[mt][0] = Ass[(mb    )*APAD + k0 + tcol];
                af[mt][1] = Ass[(mb + 8)*APAD + k0 + tcol];
                af[mt][2] = Ass[(mb    )*APAD + k0 + tcol + 4];
                af[mt][3] = Ass[(mb + 8)*APAD + k0 + tcol + 4];
            }
            #pragma unroll
            for (int nt = 0; nt < 4; nt++) {
                const int nb = n0 + nt*8 + group;
                bf[nt][0] = Wss[(k0 + tcol    )*WPAD + nb];
                bf[nt][1] = Wss[(k0 + tcol + 4)*WPAD + nb];
            }
            #pragma unroll
            for (int mt = 0; mt < 4; mt++)
                #pragma unroll
                for (int nt = 0; nt < 4; nt++)
                    mma_tf32(c[mt][nt], af[mt], bf[nt]);
        }

        __syncthreads();
        if (kt + 2 < ktiles) ISSUE_STAGE(kt + 2);
        CP_COMMIT();
    }
    #undef ISSUE_STAGE

    #pragma unroll
    for (int mt = 0; mt < 4; mt++) {
        #pragma unroll
        for (int nt = 0; nt < 4; nt++) {
            const int col = bx*128 + n0 + nt*8 + tcol*2;
            float2 bb = *(const float2*)&bias[col];
            #pragma unroll
            for (int r = 0; r < 2; r++) {
                const int row = by*128 + m0 + mt*16 + group + r*8;
                float2 v;
                v.x = c[mt][nt][r*2+0] + bb.x;
                v.y = c[mt][nt][r*2+1] + bb.y;
                if (RELU) { v.x = fmaxf(v.x, 0.f); v.y = fmaxf(v.y, 0.f); }
                float2* cp = (float2*)&C[(size_t)row*N + col];
                if (RES) { float2 o = *cp; v.x += o.x; v.y += o.y; }
                if (TFM != 1) *cp = v;
                if (TFM >= 1) {
                    uint2 t2 = { f2tf(v.x * tfscale), f2tf(v.y * tfscale) };
                    *(uint2*)&Ctf[(size_t)row*N + col] = t2;
                }
            }
        }
    }
}

template<bool RELU, bool RES, int TFM>
__global__ __launch_bounds__(256, 2) void gemm128(
    int M, int N, int K,
    const uint32_t* __restrict__ A,
    const uint32_t* __restrict__ W,
    const float* __restrict__ bias,
    float* __restrict__ C,
    uint32_t* __restrict__ Ctf)
{
    extern __shared__ uint32_t dsm[];
    gemm_core<RELU,RES,TFM>(A, W, bias, C, Ctf, 1.0f, M, N, K, blockIdx.x, blockIdx.y, dsm);
}

__global__ __launch_bounds__(256, 2) void qkv_gemm(
    const uint32_t* __restrict__ A,
    const uint32_t* __restrict__ Wq, const uint32_t* __restrict__ Wk, const uint32_t* __restrict__ Wv,
    const float* __restrict__ bq, const float* __restrict__ bk, const float* __restrict__ bv,
    uint32_t* __restrict__ q, uint32_t* __restrict__ k, uint32_t* __restrict__ v)
{
    extern __shared__ uint32_t dsm[];
    const int w   = blockIdx.x >> 2;
    const int nbx = blockIdx.x & 3;
    const uint32_t* W = (w == 0) ? Wq : (w == 1) ? Wk : Wv;
    const float*    b = (w == 0) ? bq : (w == 1) ? bk : bv;
    uint32_t*       C = (w == 0) ? q  : (w == 1) ? k  : v;
    const float    sc = (w == 0) ? 0.125f : 1.0f;
    gemm_core<false,false,1>(A, W, b, nullptr, C, sc, BT, EMB, EMB, nbx, blockIdx.y, dsm);
}

// ---------------- flash attention, cp.async double-buffered K/V ----------------
#define QS_STRIDE 68
#define KS_STRIDE 68
#define VS_STRIDE 72
#define PS_STRIDE 68
#define KV_WORDS  (64*KS_STRIDE + 64*VS_STRIDE)    // 8960 words / stage
#define ATT_SMEM_WORDS (128*QS_STRIDE + 2*KV_WORDS)
#define ATT_SMEM_BYTES (ATT_SMEM_WORDS*4)          // 106,496 B (2 CTAs/SM ok)

__global__ __launch_bounds__(256, 2) void attn_mma_kernel(
        const uint32_t* __restrict__ Q,   // tf32, pre-scaled by 0.125
        const uint32_t* __restrict__ K,   // tf32
        const uint32_t* __restrict__ V,   // tf32
        uint32_t* __restrict__ O)         // tf32 out
{
    extern __shared__ uint32_t smw[];
    uint32_t* qs  = smw;                         // 128 x QS_STRIDE (reused as ps)
    uint32_t* kv0 = qs + 128*QS_STRIDE;          // stage ring base
    uint32_t* ps  = qs;

    const int bq = blockIdx.x, hh = blockIdx.y, bb = blockIdx.z;
    const int tid = threadIdx.x, warp = tid >> 5, lane = tid & 31;
    const int g = lane >> 2, tc = lane & 3;
    const int wq = warp * 16;

    const size_t base = ((size_t)bb*SEQ)*EMB + (size_t)hh*HEADD;
    const uint32_t kvb = smem_u32(kv0);

    // per-thread staging coords: 4 passes each for K and V
    const int tok0 = tid >> 4;                   // 0..15 (+16*i)
    const int d4s  = (tid & 15) << 2;            // 0..60

    // ---- issue K/V tile kt into ring slot kt&1 ----
    #define ATT_ISSUE(kt_) do {                                                     \
        const uint32_t _so = (uint32_t)(((kt_) & 1) * KV_WORDS * 4);                \
        _Pragma("unroll")                                                           \
        for (int i = 0; i < 4; i++) {                                               \
            int _tok = tok0 + i*16;                                                 \
            CP_ASYNC16(kvb + _so + (uint32_t)(_tok*KS_STRIDE + d4s)*4,              \
                       &K[base + (size_t)((kt_)*64 + _tok)*EMB + d4s]);             \
            CP_ASYNC16(kvb + _so + (uint32_t)(64*KS_STRIDE + _tok*VS_STRIDE + d4s)*4,\
                       &V[base + (size_t)((kt_)*64 + _tok)*EMB + d4s]);             \
        }                                                                           \
    } while (0)

    // ---- stage Q, load Q fragments ----
    #pragma unroll
    for (int i = 0; i < 8; i++) {
        int f   = i*256 + tid;
        int row = f >> 4, d4 = (f & 15) << 2;
        *(uint4*)&qs[row*QS_STRIDE + d4] =
            *(const uint4*)&Q[base + (size_t)(bq*128 + row)*EMB + d4];
    }
    ATT_ISSUE(0); CP_COMMIT();
    __syncthreads();

    uint32_t qf[8][4];
    #pragma unroll
    for (int ki = 0; ki < 8; ki++) {
        int k0 = ki*8;
        qf[ki][0] = qs[(wq+g  )*QS_STRIDE + k0 + tc];
        qf[ki][1] = qs[(wq+g+8)*QS_STRIDE + k0 + tc];
        qf[ki][2] = qs[(wq+g  )*QS_STRIDE + k0 + tc + 4];
        qf[ki][3] = qs[(wq+g+8)*QS_STRIDE + k0 + tc + 4];
    }

    float o[8][4];
    #pragma unroll
    for (int nt = 0; nt < 8; nt++)
        #pragma unroll
        for (int j = 0; j < 4; j++) o[nt][j] = 0.f;
    float m0 = -1e30f, m1 = -1e30f, l0 = 0.f, l1 = 0.f;

    const int nkt = 2*bq + 2;
    for (int kt = 0; kt < nkt; kt++) {
        // issue next tile into the other slot (its prior consumer finished
        // at the end-of-iteration sync of kt-1)
        if (kt + 1 < nkt) { ATT_ISSUE(kt + 1); CP_COMMIT(); CP_WAIT1(); }
        else              { CP_WAIT0(); }
        __syncthreads();   // stage kt visible to all; also fences ps/qs reuse

        const uint32_t* ks = kv0 + (kt & 1)*KV_WORDS;
        const uint32_t* vs = ks + 64*KS_STRIDE;

        float sc[8][4];
        #pragma unroll
        for (int nt = 0; nt < 8; nt++)
            #pragma unroll
            for (int j = 0; j < 4; j++) sc[nt][j] = 0.f;

        #pragma unroll
        for (int ki = 0; ki < 8; ki++) {
            int k0 = ki*8;
            uint32_t bf[8][2];
            #pragma unroll
            for (int nt = 0; nt < 8; nt++) {
                int nb = nt*8 + g;
                bf[nt][0] = ks[nb*KS_STRIDE + k0 + tc];
                bf[nt][1] = ks[nb*KS_STRIDE + k0 + tc + 4];
            }
            #pragma unroll
            for (int nt = 0; nt < 8; nt++)
                mma_tf32(sc[nt], qf[ki], bf[nt]);
        }

        if (kt >= 2*bq) {
            const int row0 = bq*128 + wq + g;
            #pragma unroll
            for (int nt = 0; nt < 8; nt++) {
                int c0 = kt*64 + nt*8 + 2*tc;
                if (c0     > row0    ) sc[nt][0] = -1e30f;
                if (c0 + 1 > row0    ) sc[nt][1] = -1e30f;
                if (c0     > row0 + 8) sc[nt][2] = -1e30f;
                if (c0 + 1 > row0 + 8) sc[nt][3] = -1e30f;
            }
        }

        float r0 = -1e30f, r1 = -1e30f;
        #pragma unroll
        for (int nt = 0; nt < 8; nt++) {
            r0 = fmaxf(r0, fmaxf(sc[nt][0], sc[nt][1]));
            r1 = fmaxf(r1, fmaxf(sc[nt][2], sc[nt][3]));
        }
        r0 = fmaxf(r0, __shfl_xor_sync(0xffffffffu, r0, 1));
        r0 = fmaxf(r0, __shfl_xor_sync(0xffffffffu, r0, 2));
        r1 = fmaxf(r1, __shfl_xor_sync(0xffffffffu, r1, 1));
        r1 = fmaxf(r1, __shfl_xor_sync(0xffffffffu, r1, 2));

        float mn0 = fmaxf(m0, r0), mn1 = fmaxf(m1, r1);
        float cor0 = __expf(m0 - mn0), cor1 = __expf(m1 - mn1);
        m0 = mn0; m1 = mn1;
        l0 *= cor0; l1 *= cor1;
        #pragma unroll
        for (int nt = 0; nt < 8; nt++) {
            o[nt][0] *= cor0; o[nt][1] *= cor0;
            o[nt][2] *= cor1; o[nt][3] *= cor1;
        }

        float s0 = 0.f, s1 = 0.f;
        #pragma unroll
        for (int nt = 0; nt < 8; nt++) {
            float p00 = __expf(sc[nt][0] - mn0);
            float p01 = __expf(sc[nt][1] - mn0);
            float p10 = __expf(sc[nt][2] - mn1);
            float p11 = __expf(sc[nt][3] - mn1);
            s0 += p00 + p01; s1 += p10 + p11;
            int col = nt*8 + 2*tc;
            ps[(wq+g  )*PS_STRIDE + col    ] = f2tf(p00);
            ps[(wq+g  )*PS_STRIDE + col + 1] = f2tf(p01);
            ps[(wq+g+8)*PS_STRIDE + col    ] = f2tf(p10);
            ps[(wq+g+8)*PS_STRIDE + col + 1] = f2tf(p11);
        }
        s0 += __shfl_xor_sync(0xffffffffu, s0, 1);
        s0 += __shfl_xor_sync(0xffffffffu, s0, 2);
        s1 += __shfl_xor_sync(0xffffffffu, s1, 1);
        s1 += __shfl_xor_sync(0xffffffffu, s1, 2);
        l0 += s0; l1 += s1;
        __syncwarp();   // ps region is per-warp private

        #pragma unroll
        for (int ki = 0; ki < 8; ki++) {
            int k0 = ki*8;
            uint32_t af[4];
            af[0] = ps[(wq+g  )*PS_STRIDE + k0 + tc];
            af[1] = ps[(wq+g+8)*PS_STRIDE + k0 + tc];
            af[2] = ps[(wq+g  )*PS_STRIDE + k0 + tc + 4];
            af[3] = ps[(wq+g+8)*PS_STRIDE + k0 + tc + 4];
            uint32_t bf[8][2];
            #pragma unroll
            for (int nt = 0; nt < 8; nt++) {
                int nb = nt*8 + g;
                bf[nt][0] = vs[(k0 + tc    )*VS_STRIDE + nb];
                bf[nt][1] = vs[(k0 + tc + 4)*VS_STRIDE + nb];
            }
            #pragma unroll
            for (int nt = 0; nt < 8; nt++)
                mma_tf32(o[nt], af, bf[nt]);
        }
        __syncthreads();   // all warps done with stage kt&1 before reissue
    }
    #undef ATT_ISSUE

    float inv0 = 1.0f / l0, inv1 = 1.0f / l1;
    const int row0 = bq*128 + wq + g;
    #pragma unroll
    for (int nt = 0; nt < 8; nt++) {
        int d = nt*8 + 2*tc;
        uint2 a = { f2tf(o[nt][0]*inv0), f2tf(o[nt][1]*inv0) };
        *(uint2*)&O[base + (size_t)row0*EMB + d] = a;
        uint2 b = { f2tf(o[nt][2]*inv1), f2tf(o[nt][3]*inv1) };
        *(uint2*)&O[base + (size_t)(row0+8)*EMB + d] = b;
    }
}

// ---------------- orchestration ----------------
extern "C" void kernel_launch(void* const* d_in, const int* in_sizes, int n_in,
                              void* d_out, int out_size)
{
    (void)in_sizes; (void)n_in;
    const int*   x       = (const int*)  d_in[0];
    const float* tok_emb = (const float*)d_in[1];
    const float* pos_emb = (const float*)d_in[2];
    const float* Wq   = (const float*)d_in[3];
    const float* bq   = (const float*)d_in[4];
    const float* Wk   = (const float*)d_in[5];
    const float* bk   = (const float*)d_in[6];
    const float* Wv   = (const float*)d_in[7];
    const float* bv   = (const float*)d_in[8];
    const float* Wo   = (const float*)d_in[9];
    const float* bo   = (const float*)d_in[10];
    const float* ln1s = (const float*)d_in[11];
    const float* ln1b = (const float*)d_in[12];
    const float* ln2s = (const float*)d_in[13];
    const float* ln2b = (const float*)d_in[14];
    const float* W1   = (const float*)d_in[15];
    const float* b1   = (const float*)d_in[16];
    const float* W2   = (const float*)d_in[17];
    const float* b2   = (const float*)d_in[18];
    const float* Wout = (const float*)d_in[19];
    const float* bout = (const float*)d_in[20];
    float* out = (float*)d_out;
    (void)out_size;

    float *h; uint32_t *y, *q, *k, *v, *o, *ff, *htf, *wtf;
    cudaGetSymbolAddress((void**)&h,   g_h);
    cudaGetSymbolAddress((void**)&y,   g_y);
    cudaGetSymbolAddress((void**)&q,   g_q);
    cudaGetSymbolAddress((void**)&k,   g_k);
    cudaGetSymbolAddress((void**)&v,   g_v);
    cudaGetSymbolAddress((void**)&o,   g_o);
    cudaGetSymbolAddress((void**)&ff,  g_ff);
    cudaGetSymbolAddress((void**)&htf, g_htf);
    cudaGetSymbolAddress((void**)&wtf, g_wtf);

    cudaFuncSetAttribute(gemm128<false,false,0>,
        cudaFuncAttributeMaxDynamicSharedMemorySize, GEMM_SMEM_BYTES);
    cudaFuncSetAttribute(gemm128<false,true,0>,
        cudaFuncAttributeMaxDynamicSharedMemorySize, GEMM_SMEM_BYTES);
    cudaFuncSetAttribute(gemm128<false,true,2>,
        cudaFuncAttributeMaxDynamicSharedMemorySize, GEMM_SMEM_BYTES);
    cudaFuncSetAttribute(gemm128<true,false,1>,
        cudaFuncAttributeMaxDynamicSharedMemorySize, GEMM_SMEM_BYTES);
    cudaFuncSetAttribute(qkv_gemm,
        cudaFuncAttributeMaxDynamicSharedMemorySize, GEMM_SMEM_BYTES);
    cudaFuncSetAttribute(attn_mma_kernel,
        cudaFuncAttributeMaxDynamicSharedMemorySize, ATT_SMEM_BYTES);

    // ---- one-time weight conversion to tf32 ----
    {
        const int T = 256;
        cvt_tf_kernel<<<EE6/(4*T), T>>>(Wq,   wtf + OFF_WQ,   EE6);
        cvt_tf_kernel<<<EE6/(4*T), T>>>(Wk,   wtf + OFF_WK,   EE6);
        cvt_tf_kernel<<<EE6/(4*T), T>>>(Wv,   wtf + OFF_WV,   EE6);
        cvt_tf_kernel<<<EE6/(4*T), T>>>(Wo,   wtf + OFF_WO,   EE6);
        cvt_tf_kernel<<<EF6/(4*T), T>>>(W1,   wtf + OFF_W1,   EF6);
        cvt_tf_kernel<<<EF6/(4*T), T>>>(W2,   wtf + OFF_W2,   EF6);
        cvt_tf_kernel<<<(EMB*VOCAB)/(4*T), T>>>(Wout, wtf + OFF_WOUT, EMB*VOCAB);
    }

    const int M = BT;
    embed_kernel<<<BT, 128>>>(x, tok_emb, pos_emb, h);

    for (int i = 0; i < NLAYER; i++) {
        const uint32_t* Wqi = wtf + OFF_WQ + (size_t)i*EMB*EMB;
        const uint32_t* Wki = wtf + OFF_WK + (size_t)i*EMB*EMB;
        const uint32_t* Wvi = wtf + OFF_WV + (size_t)i*EMB*EMB;
        const uint32_t* Woi = wtf + OFF_WO + (size_t)i*EMB*EMB;
        const uint32_t* W1i = wtf + OFF_W1 + (size_t)i*EMB*FFDIM;
        const uint32_t* W2i = wtf + OFF_W2 + (size_t)i*FFDIM*EMB;

        ln_kernel<<<BT, 128>>>(h, ln1s + i*EMB, ln1b + i*EMB, y);

        qkv_gemm<<<dim3(12, M/128), 256, GEMM_SMEM_BYTES>>>(
            y, Wqi, Wki, Wvi, bq + i*EMB, bk + i*EMB, bv + i*EMB, q, k, v);

        attn_mma_kernel<<<dim3(SEQ/128, NHEAD, BATCH), 256, ATT_SMEM_BYTES>>>(q, k, v, o);

        gemm128<false,true,0><<<dim3(EMB/128, M/128), 256, GEMM_SMEM_BYTES>>>(
            M, EMB, EMB, o, Woi, bo + i*EMB, h, nullptr);

        ln_kernel<<<BT, 128>>>(h, ln2s + i*EMB, ln2b + i*EMB, y);

        gemm128<true,false,1><<<dim3(FFDIM/128, M/128), 256, GEMM_SMEM_BYTES>>>(
            M, FFDIM, EMB, y, W1i, b1 + i*FFDIM, nullptr, ff);

        if (i < NLAYER - 1) {
            gemm128<false,true,0><<<dim3(EMB/128, M/128), 256, GEMM_SMEM_BYTES>>>(
                M, EMB, FFDIM, ff, W2i, b2 + i*EMB, h, nullptr);
        } else {
            gemm128<false,true,2><<<dim3(EMB/128, M/128), 256, GEMM_SMEM_BYTES>>>(
                M, EMB, FFDIM, ff, W2i, b2 + i*EMB, h, htf);
        }
    }

    gemm128<false,false,0><<<dim3(VOCAB/128, M/128), 256, GEMM_SMEM_BYTES>>>(
        M, VOCAB, EMB, htf, wtf + OFF_WOUT, bout, out, nullptr);
}

// round 11
// speedup vs baseline: 1.5080x; 1.1127x over previous
#include <cuda_runtime.h>
#include <cuda_bf16.h>
#include <math.h>
#include <stdint.h>

// ---------------- problem constants ----------------
#define VOCAB 32000
#define EMB   512
#define SEQ   2048
#define NHEAD 8
#define NLAYER 6
#define FFDIM 2048
#define BATCH 2
#define HEADD 64
#define BT    (BATCH*SEQ)      // 4096 tokens
#define EPS_LN 1e-5f

// ---------------- scratch (device globals; no allocation allowed) ----------------
__device__ float    g_h  [BT*EMB];     // residual stream (fp32)
__device__ uint32_t g_y  [BT*EMB];     // LN output (tf32)
__device__ uint32_t g_q  [BT*EMB];     // tf32, pre-scaled by 0.125
__device__ uint32_t g_k  [BT*EMB];     // tf32
__device__ uint32_t g_v  [BT*EMB];     // tf32
__device__ uint32_t g_o  [BT*EMB];     // attention output (tf32)
__device__ uint32_t g_ff [BT*FFDIM];   // FFN hidden (tf32)
__device__ uint32_t g_htf[BT*EMB];     // final residual (tf32) for vocab gemm

// tf32 weight mirror, same [K][N] layout as inputs
#define EE6 (NLAYER*EMB*EMB)
#define EF6 (NLAYER*EMB*FFDIM)
#define OFF_WQ   0
#define OFF_WK   (EE6)
#define OFF_WV   (2*EE6)
#define OFF_WO   (3*EE6)
#define OFF_W1   (4*EE6)
#define OFF_W2   (4*EE6 + EF6)
#define OFF_WOUT (4*EE6 + 2*EF6)
#define WTF_TOTAL (4*EE6 + 2*EF6 + EMB*VOCAB)
__device__ uint32_t g_wtf[WTF_TOTAL];

// ---------------- helpers ----------------
__device__ __forceinline__ uint32_t f2tf(float f) {
    uint32_t u; asm("cvt.rna.tf32.f32 %0, %1;" : "=r"(u) : "f"(f)); return u;
}
__device__ __forceinline__ void mma_tf32(float* c, const uint32_t* a, const uint32_t* b) {
    asm volatile(
        "mma.sync.aligned.m16n8k8.row.col.f32.tf32.tf32.f32 "
        "{%0,%1,%2,%3}, {%4,%5,%6,%7}, {%8,%9}, {%0,%1,%2,%3};\n"
        : "+f"(c[0]), "+f"(c[1]), "+f"(c[2]), "+f"(c[3])
        : "r"(a[0]), "r"(a[1]), "r"(a[2]), "r"(a[3]),
          "r"(b[0]), "r"(b[1]));
}
__device__ __forceinline__ uint32_t smem_u32(const void* p) {
    uint32_t a;
    asm("{ .reg .u64 t; cvta.to.shared.u64 t, %1; cvt.u32.u64 %0, t; }" : "=r"(a) : "l"(p));
    return a;
}
#define CP_ASYNC16(dst, src) \
    asm volatile("cp.async.cg.shared.global [%0], [%1], 16;" :: "r"(dst), "l"(src))
#define CP_COMMIT() asm volatile("cp.async.commit_group;" ::: "memory")
#define CP_WAIT1()  asm volatile("cp.async.wait_group 1;" ::: "memory")
#define CP_WAIT0()  asm volatile("cp.async.wait_group 0;" ::: "memory")

// ---------------- one-time weight convert fp32 -> tf32 ----------------
__global__ void cvt_tf_kernel(const float* __restrict__ s, uint32_t* __restrict__ d, int n)
{
    int i = (blockIdx.x * 256 + threadIdx.x) * 4;
    if (i < n) {
        float4 v = *(const float4*)&s[i];
        uint4 u = { f2tf(v.x), f2tf(v.y), f2tf(v.z), f2tf(v.w) };
        *(uint4*)&d[i] = u;
    }
}

// ---------------- embedding ----------------
__global__ void embed_kernel(const int* __restrict__ x,
                             const float* __restrict__ tok,
                             const float* __restrict__ pos,
                             float* __restrict__ h)
{
    int row = blockIdx.x;
    int t   = row % SEQ;
    int id  = x[row];
    const float* te = tok + (size_t)id * EMB;
    const float* pe = pos + (size_t)t  * EMB;
    float* out = h + (size_t)row * EMB;
    for (int i = threadIdx.x; i < EMB; i += blockDim.x)
        out[i] = te[i] + pe[i];
}

// ---------------- layernorm (emits tf32 directly) ----------------
__global__ void ln_kernel(const float* __restrict__ X,
                          const float* __restrict__ scale,
                          const float* __restrict__ bias,
                          uint32_t* __restrict__ Y)
{
    int row = blockIdx.x;
    int t = threadIdx.x;                   // 128 threads
    const float* x = X + (size_t)row * EMB;
    uint32_t* y = Y + (size_t)row * EMB;

    float s = 0.f, sq = 0.f;
    #pragma unroll
    for (int i = t; i < EMB; i += 128) { float v = x[i]; s += v; sq += v*v; }

    __shared__ float r1[128], r2[128];
    r1[t] = s; r2[t] = sq;
    __syncthreads();
    for (int k = 64; k > 0; k >>= 1) {
        if (t < k) { r1[t] += r1[t+k]; r2[t] += r2[t+k]; }
        __syncthreads();
    }
    float mean = r1[0] * (1.0f/EMB);
    float var  = r2[0] * (1.0f/EMB) - mean*mean;
    float rstd = rsqrtf(var + EPS_LN);

    #pragma unroll
    for (int i = t; i < EMB; i += 128)
        y[i] = f2tf((x[i] - mean) * rstd * scale[i] + bias[i]);
}

// ---------------- tf32 GEMM, cp.async 3-stage, single barrier per k-tile ----------------
#define APAD 36
#define WPAD 136
#define STG_WORDS (128*APAD + 32*WPAD)
#define NSTAGE 3
#define GEMM_SMEM_BYTES (NSTAGE*STG_WORDS*4)   // 107520 B

template<bool RELU, bool RES, int TFM>
__device__ __forceinline__ void gemm_core(
    const uint32_t* __restrict__ A,
    const uint32_t* __restrict__ W,
    const float* __restrict__ bias,
    float* __restrict__ C,
    uint32_t* __restrict__ Ctf,
    float tfscale,
    int M, int N, int K, int bx, int by, uint32_t* dsm)
{
    const int tid  = threadIdx.x;
    const int warp = tid >> 5, lane = tid & 31;
    const int m0   = (warp & 1) * 64;
    const int n0   = (warp >> 1) * 32;
    const int group = lane >> 2, tcol = lane & 3;

    const int aRow = tid >> 3;
    const int aCol = (tid & 7) << 2;
    const int wRow = tid >> 3;
    const int wCol = (tid & 7) << 2;

    const uint32_t smb = smem_u32(dsm);
    const uint32_t aDst = smb + (uint32_t)(aRow*APAD + aCol)*4;
    const uint32_t wDst = smb + (uint32_t)(128*APAD + wRow*WPAD + wCol)*4;

    float c[4][4][4];
    #pragma unroll
    for (int mt = 0; mt < 4; mt++)
        #pragma unroll
        for (int nt = 0; nt < 4; nt++)
            #pragma unroll
            for (int j = 0; j < 4; j++) c[mt][nt][j] = 0.f;

    const int ktiles = K >> 5;

    #define ISSUE_STAGE(kt_) do {                                              \
        const int _kb = (kt_) << 5;                                            \
        const uint32_t _so = (uint32_t)(((kt_) % NSTAGE) * STG_WORDS * 4);     \
        _Pragma("unroll")                                                      \
        for (int i = 0; i < 4; i++)                                            \
            CP_ASYNC16(aDst + _so + (uint32_t)(i*32*APAD)*4,                   \
                       &A[(size_t)(by*128 + aRow + i*32)*K + _kb + aCol]);     \
        _Pragma("unroll")                                                      \
        for (int i = 0; i < 4; i++)                                            \
            CP_ASYNC16(wDst + _so + (uint32_t)(i*32)*4,                        \
                       &W[(size_t)(_kb + wRow)*N + bx*128 + wCol + i*32]);     \
    } while (0)

    ISSUE_STAGE(0); CP_COMMIT();
    ISSUE_STAGE(1); CP_COMMIT();

    for (int kt = 0; kt < ktiles; kt++) {
        CP_WAIT1();          // tile kt resident (tile kt+1 may be in flight)
        __syncthreads();     // (a) staging visible to all (b) all finished compute kt-1

        // issue kt+2 into slot kt%3's sibling ((kt+2)%3): its consumers (kt-1)
        // all passed the barrier above, so the slot is free.
        if (kt + 2 < ktiles) ISSUE_STAGE(kt + 2);
        CP_COMMIT();

        const uint32_t* Ass = dsm + (kt % NSTAGE)*STG_WORDS;
        const uint32_t* Wss = Ass + 128*APAD;

        #pragma unroll
        for (int ks = 0; ks < 4; ks++) {
            const int k0 = ks << 3;
            uint32_t af[4][4], bf[4][2];
            #pragma unroll
            for (int mt = 0; mt < 4; mt++) {
                const int mb = m0 + mt*16 + group;
                af[mt][0] = Ass[(mb    )*APAD + k0 + tcol];
                af[mt][1] = Ass[(mb + 8)*APAD + k0 + tcol];
                af[mt][2] = Ass[(mb    )*APAD + k0 + tcol + 4];
                af[mt][3] = Ass[(mb + 8)*APAD + k0 + tcol + 4];
            }
            #pragma unroll
            for (int nt = 0; nt < 4; nt++) {
                const int nb = n0 + nt*8 + group;
                bf[nt][0] = Wss[(k0 + tcol    )*WPAD + nb];
                bf[nt][1] = Wss[(k0 + tcol + 4)*WPAD + nb];
            }
            #pragma unroll
            for (int mt = 0; mt < 4; mt++)
                #pragma unroll
                for (int nt = 0; nt < 4; nt++)
                    mma_tf32(c[mt][nt], af[mt], bf[nt]);
        }
    }
    #undef ISSUE_STAGE

    #pragma unroll
    for (int mt = 0; mt < 4; mt++) {
        #pragma unroll
        for (int nt = 0; nt < 4; nt++) {
            const int col = bx*128 + n0 + nt*8 + tcol*2;
            float2 bb = *(const float2*)&bias[col];
            #pragma unroll
            for (int r = 0; r < 2; r++) {
                const int row = by*128 + m0 + mt*16 + group + r*8;
                float2 v;
                v.x = c[mt][nt][r*2+0] + bb.x;
                v.y = c[mt][nt][r*2+1] + bb.y;
                if (RELU) { v.x = fmaxf(v.x, 0.f); v.y = fmaxf(v.y, 0.f); }
                float2* cp = (float2*)&C[(size_t)row*N + col];
                if (RES) { float2 o = *cp; v.x += o.x; v.y += o.y; }
                if (TFM != 1) *cp = v;
                if (TFM >= 1) {
                    uint2 t2 = { f2tf(v.x * tfscale), f2tf(v.y * tfscale) };
                    *(uint2*)&Ctf[(size_t)row*N + col] = t2;
                }
            }
        }
    }
}

template<bool RELU, bool RES, int TFM>
__global__ __launch_bounds__(256, 2) void gemm128(
    int M, int N, int K,
    const uint32_t* __restrict__ A,
    const uint32_t* __restrict__ W,
    const float* __restrict__ bias,
    float* __restrict__ C,
    uint32_t* __restrict__ Ctf)
{
    extern __shared__ uint32_t dsm[];
    gemm_core<RELU,RES,TFM>(A, W, bias, C, Ctf, 1.0f, M, N, K, blockIdx.x, blockIdx.y, dsm);
}

__global__ __launch_bounds__(256, 2) void qkv_gemm(
    const uint32_t* __restrict__ A,
    const uint32_t* __restrict__ Wq, const uint32_t* __restrict__ Wk, const uint32_t* __restrict__ Wv,
    const float* __restrict__ bq, const float* __restrict__ bk, const float* __restrict__ bv,
    uint32_t* __restrict__ q, uint32_t* __restrict__ k, uint32_t* __restrict__ v)
{
    extern __shared__ uint32_t dsm[];
    const int w   = blockIdx.x >> 2;
    const int nbx = blockIdx.x & 3;
    const uint32_t* W = (w == 0) ? Wq : (w == 1) ? Wk : Wv;
    const float*    b = (w == 0) ? bq : (w == 1) ? bk : bv;
    uint32_t*       C = (w == 0) ? q  : (w == 1) ? k  : v;
    const float    sc = (w == 0) ? 0.125f : 1.0f;
    gemm_core<false,false,1>(A, W, b, nullptr, C, sc, BT, EMB, EMB, nbx, blockIdx.y, dsm);
}

// ---------------- flash attention: diagonal-paired 64-query tiles ----------------
// 128 threads = 4 warps, each warp 16 q-rows (same per-warp code as before).
// CTA p processes q-tile p then q-tile 31-p: (p+1)+(32-p)=33 key-tiles, constant
// across all 256 CTAs -> perfectly balanced single wave.
#define QS_STRIDE 68
#define KS_STRIDE 68
#define VS_STRIDE 72
#define PS_STRIDE 68
#define KV_WORDS  (64*KS_STRIDE + 64*VS_STRIDE)        // 8960 words / stage
#define ATT_SMEM_WORDS (64*QS_STRIDE + 2*KV_WORDS)     // 22272 words
#define ATT_SMEM_BYTES (ATT_SMEM_WORDS*4)              // 89088 B -> 2 CTAs/SM

#define NQT (SEQ/64)    // 32 q-tiles

__global__ __launch_bounds__(128, 2) void attn_mma_kernel(
        const uint32_t* __restrict__ Q,   // tf32, pre-scaled by 0.125
        const uint32_t* __restrict__ K,   // tf32
        const uint32_t* __restrict__ V,   // tf32
        uint32_t* __restrict__ O)         // tf32 out
{
    extern __shared__ uint32_t smw[];
    uint32_t* qs  = smw;                         // 64 x QS_STRIDE (reused as ps)
    uint32_t* kv0 = qs + 64*QS_STRIDE;           // 2-stage K/V ring
    uint32_t* ps  = qs;

    const int pair = blockIdx.x, hh = blockIdx.y, bb = blockIdx.z;
    const int tid = threadIdx.x, warp = tid >> 5, lane = tid & 31;
    const int g = lane >> 2, tc = lane & 3;
    const int wq = warp * 16;                    // warp covers rows wq..wq+15 of the 64

    const size_t base = ((size_t)bb*SEQ)*EMB + (size_t)hh*HEADD;
    const uint32_t kvb = smem_u32(kv0);

    const int tok0 = tid >> 4;                   // 0..7 (+8*i)
    const int d4s  = (tid & 15) << 2;            // 0..60

    #define ATT_ISSUE(kt_) do {                                                     \
        const uint32_t _so = (uint32_t)(((kt_) & 1) * KV_WORDS * 4);                \
        _Pragma("unroll")                                                           \
        for (int i = 0; i < 8; i++) {                                               \
            int _tok = tok0 + i*8;                                                  \
            CP_ASYNC16(kvb + _so + (uint32_t)(_tok*KS_STRIDE + d4s)*4,              \
                       &K[base + (size_t)((kt_)*64 + _tok)*EMB + d4s]);             \
            CP_ASYNC16(kvb + _so + (uint32_t)(64*KS_STRIDE + _tok*VS_STRIDE + d4s)*4,\
                       &V[base + (size_t)((kt_)*64 + _tok)*EMB + d4s]);             \
        }                                                                           \
    } while (0)

    for (int phase = 0; phase < 2; phase++) {
        const int qt  = phase ? (NQT - 1 - pair) : pair;
        const int nkt = qt + 1;

        // ---- stage Q tile (64 rows x 16 uint4) ----
        #pragma unroll
        for (int i = 0; i < 8; i++) {
            int f   = i*128 + tid;
            int row = f >> 4, d4 = (f & 15) << 2;
            *(uint4*)&qs[row*QS_STRIDE + d4] =
                *(const uint4*)&Q[base + (size_t)(qt*64 + row)*EMB + d4];
        }
        ATT_ISSUE(0); CP_COMMIT();
        __syncthreads();

        uint32_t qf[8][4];
        #pragma unroll
        for (int ki = 0; ki < 8; ki++) {
            int k0 = ki*8;
            qf[ki][0] = qs[(wq+g  )*QS_STRIDE + k0 + tc];
            qf[ki][1] = qs[(wq+g+8)*QS_STRIDE + k0 + tc];
            qf[ki][2] = qs[(wq+g  )*QS_STRIDE + k0 + tc + 4];
            qf[ki][3] = qs[(wq+g+8)*QS_STRIDE + k0 + tc + 4];
        }

        float o[8][4];
        #pragma unroll
        for (int nt = 0; nt < 8; nt++)
            #pragma unroll
            for (int j = 0; j < 4; j++) o[nt][j] = 0.f;
        float m0 = -1e30f, m1 = -1e30f, l0 = 0.f, l1 = 0.f;

        for (int kt = 0; kt < nkt; kt++) {
            if (kt + 1 < nkt) { ATT_ISSUE(kt + 1); CP_COMMIT(); CP_WAIT1(); }
            else              { CP_WAIT0(); }
            __syncthreads();

            const uint32_t* ks = kv0 + (kt & 1)*KV_WORDS;
            const uint32_t* vs = ks + 64*KS_STRIDE;

            float sc[8][4];
            #pragma unroll
            for (int nt = 0; nt < 8; nt++)
                #pragma unroll
                for (int j = 0; j < 4; j++) sc[nt][j] = 0.f;

            #pragma unroll
            for (int ki = 0; ki < 8; ki++) {
                int k0 = ki*8;
                uint32_t bf[8][2];
                #pragma unroll
                for (int nt = 0; nt < 8; nt++) {
                    int nb = nt*8 + g;
                    bf[nt][0] = ks[nb*KS_STRIDE + k0 + tc];
                    bf[nt][1] = ks[nb*KS_STRIDE + k0 + tc + 4];
                }
                #pragma unroll
                for (int nt = 0; nt < 8; nt++)
                    mma_tf32(sc[nt], qf[ki], bf[nt]);
            }

            if (kt >= qt) {   // only the diagonal tile needs masking
                const int row0 = qt*64 + wq + g;
                #pragma unroll
                for (int nt = 0; nt < 8; nt++) {
                    int c0 = kt*64 + nt*8 + 2*tc;
                    if (c0     > row0    ) sc[nt][0] = -1e30f;
                    if (c0 + 1 > row0    ) sc[nt][1] = -1e30f;
                    if (c0     > row0 + 8) sc[nt][2] = -1e30f;
                    if (c0 + 1 > row0 + 8) sc[nt][3] = -1e30f;
                }
            }

            float r0 = -1e30f, r1 = -1e30f;
            #pragma unroll
            for (int nt = 0; nt < 8; nt++) {
                r0 = fmaxf(r0, fmaxf(sc[nt][0], sc[nt][1]));
                r1 = fmaxf(r1, fmaxf(sc[nt][2], sc[nt][3]));
            }
            r0 = fmaxf(r0, __shfl_xor_sync(0xffffffffu, r0, 1));
            r0 = fmaxf(r0, __shfl_xor_sync(0xffffffffu, r0, 2));
            r1 = fmaxf(r1, __shfl_xor_sync(0xffffffffu, r1, 1));
            r1 = fmaxf(r1, __shfl_xor_sync(0xffffffffu, r1, 2));

            float mn0 = fmaxf(m0, r0), mn1 = fmaxf(m1, r1);
            float cor0 = __expf(m0 - mn0), cor1 = __expf(m1 - mn1);
            m0 = mn0; m1 = mn1;
            l0 *= cor0; l1 *= cor1;
            #pragma unroll
            for (int nt = 0; nt < 8; nt++) {
                o[nt][0] *= cor0; o[nt][1] *= cor0;
                o[nt][2] *= cor1; o[nt][3] *= cor1;
            }

            float s0 = 0.f, s1 = 0.f;
            #pragma unroll
            for (int nt = 0; nt < 8; nt++) {
                float p00 = __expf(sc[nt][0] - mn0);
                float p01 = __expf(sc[nt][1] - mn0);
                float p10 = __expf(sc[nt][2] - mn1);
                float p11 = __expf(sc[nt][3] - mn1);
                s0 += p00 + p01; s1 += p10 + p11;
                int col = nt*8 + 2*tc;
                ps[(wq+g  )*PS_STRIDE + col    ] = f2tf(p00);
                ps[(wq+g  )*PS_STRIDE + col + 1] = f2tf(p01);
                ps[(wq+g+8)*PS_STRIDE + col    ] = f2tf(p10);
                ps[(wq+g+8)*PS_STRIDE + col + 1] = f2tf(p11);
            }
            s0 += __shfl_xor_sync(0xffffffffu, s0, 1);
            s0 += __shfl_xor_sync(0xffffffffu, s0, 2);
            s1 += __shfl_xor_sync(0xffffffffu, s1, 1);
            s1 += __shfl_xor_sync(0xffffffffu, s1, 2);
            l0 += s0; l1 += s1;
            __syncwarp();   // ps rows are per-warp private

            #pragma unroll
            for (int ki = 0; ki < 8; ki++) {
                int k0 = ki*8;
                uint32_t af[4];
                af[0] = ps[(wq+g  )*PS_STRIDE + k0 + tc];
                af[1] = ps[(wq+g+8)*PS_STRIDE + k0 + tc];
                af[2] = ps[(wq+g  )*PS_STRIDE + k0 + tc + 4];
                af[3] = ps[(wq+g+8)*PS_STRIDE + k0 + tc + 4];
                uint32_t bf[8][2];
                #pragma unroll
                for (int nt = 0; nt < 8; nt++) {
                    int nb = nt*8 + g;
                    bf[nt][0] = vs[(k0 + tc    )*VS_STRIDE + nb];
                    bf[nt][1] = vs[(k0 + tc + 4)*VS_STRIDE + nb];
                }
                #pragma unroll
                for (int nt = 0; nt < 8; nt++)
                    mma_tf32(o[nt], af, bf[nt]);
            }
            __syncthreads();   // all warps done with this K/V slot before reissue
        }

        // ---- epilogue for this q-tile ----
        float inv0 = 1.0f / l0, inv1 = 1.0f / l1;
        const int row0 = qt*64 + wq + g;
        #pragma unroll
        for (int nt = 0; nt < 8; nt++) {
            int d = nt*8 + 2*tc;
            uint2 a = { f2tf(o[nt][0]*inv0), f2tf(o[nt][1]*inv0) };
            *(uint2*)&O[base + (size_t)row0*EMB + d] = a;
            uint2 b = { f2tf(o[nt][2]*inv1), f2tf(o[nt][3]*inv1) };
            *(uint2*)&O[base + (size_t)(row0+8)*EMB + d] = b;
        }
        __syncthreads();   // protect qs/ps before next phase overwrites Q
    }
    #undef ATT_ISSUE
}

// ---------------- orchestration ----------------
extern "C" void kernel_launch(void* const* d_in, const int* in_sizes, int n_in,
                              void* d_out, int out_size)
{
    (void)in_sizes; (void)n_in;
    const int*   x       = (const int*)  d_in[0];
    const float* tok_emb = (const float*)d_in[1];
    const float* pos_emb = (const float*)d_in[2];
    const float* Wq   = (const float*)d_in[3];
    const float* bq   = (const float*)d_in[4];
    const float* Wk   = (const float*)d_in[5];
    const float* bk   = (const float*)d_in[6];
    const float* Wv   = (const float*)d_in[7];
    const float* bv   = (const float*)d_in[8];
    const float* Wo   = (const float*)d_in[9];
    const float* bo   = (const float*)d_in[10];
    const float* ln1s = (const float*)d_in[11];
    const float* ln1b = (const float*)d_in[12];
    const float* ln2s = (const float*)d_in[13];
    const float* ln2b = (const float*)d_in[14];
    const float* W1   = (const float*)d_in[15];
    const float* b1   = (const float*)d_in[16];
    const float* W2   = (const float*)d_in[17];
    const float* b2   = (const float*)d_in[18];
    const float* Wout = (const float*)d_in[19];
    const float* bout = (const float*)d_in[20];
    float* out = (float*)d_out;
    (void)out_size;

    float *h; uint32_t *y, *q, *k, *v, *o, *ff, *htf, *wtf;
    cudaGetSymbolAddress((void**)&h,   g_h);
    cudaGetSymbolAddress((void**)&y,   g_y);
    cudaGetSymbolAddress((void**)&q,   g_q);
    cudaGetSymbolAddress((void**)&k,   g_k);
    cudaGetSymbolAddress((void**)&v,   g_v);
    cudaGetSymbolAddress((void**)&o,   g_o);
    cudaGetSymbolAddress((void**)&ff,  g_ff);
    cudaGetSymbolAddress((void**)&htf, g_htf);
    cudaGetSymbolAddress((void**)&wtf, g_wtf);

    cudaFuncSetAttribute(gemm128<false,false,0>,
        cudaFuncAttributeMaxDynamicSharedMemorySize, GEMM_SMEM_BYTES);
    cudaFuncSetAttribute(gemm128<false,true,0>,
        cudaFuncAttributeMaxDynamicSharedMemorySize, GEMM_SMEM_BYTES);
    cudaFuncSetAttribute(gemm128<false,true,2>,
        cudaFuncAttributeMaxDynamicSharedMemorySize, GEMM_SMEM_BYTES);
    cudaFuncSetAttribute(gemm128<true,false,1>,
        cudaFuncAttributeMaxDynamicSharedMemorySize, GEMM_SMEM_BYTES);
    cudaFuncSetAttribute(qkv_gemm,
        cudaFuncAttributeMaxDynamicSharedMemorySize, GEMM_SMEM_BYTES);
    cudaFuncSetAttribute(attn_mma_kernel,
        cudaFuncAttributeMaxDynamicSharedMemorySize, ATT_SMEM_BYTES);

    // ---- one-time weight conversion to tf32 ----
    {
        const int T = 256;
        cvt_tf_kernel<<<EE6/(4*T), T>>>(Wq,   wtf + OFF_WQ,   EE6);
        cvt_tf_kernel<<<EE6/(4*T), T>>>(Wk,   wtf + OFF_WK,   EE6);
        cvt_tf_kernel<<<EE6/(4*T), T>>>(Wv,   wtf + OFF_WV,   EE6);
        cvt_tf_kernel<<<EE6/(4*T), T>>>(Wo,   wtf + OFF_WO,   EE6);
        cvt_tf_kernel<<<EF6/(4*T), T>>>(W1,   wtf + OFF_W1,   EF6);
        cvt_tf_kernel<<<EF6/(4*T), T>>>(W2,   wtf + OFF_W2,   EF6);
        cvt_tf_kernel<<<(EMB*VOCAB)/(4*T), T>>>(Wout, wtf + OFF_WOUT, EMB*VOCAB);
    }

    const int M = BT;
    embed_kernel<<<BT, 128>>>(x, tok_emb, pos_emb, h);

    for (int i = 0; i < NLAYER; i++) {
        const uint32_t* Wqi = wtf + OFF_WQ + (size_t)i*EMB*EMB;
        const uint32_t* Wki = wtf + OFF_WK + (size_t)i*EMB*EMB;
        const uint32_t* Wvi = wtf + OFF_WV + (size_t)i*EMB*EMB;
        const uint32_t* Woi = wtf + OFF_WO + (size_t)i*EMB*EMB;
        const uint32_t* W1i = wtf + OFF_W1 + (size_t)i*EMB*FFDIM;
        const uint32_t* W2i = wtf + OFF_W2 + (size_t)i*FFDIM*EMB;

        ln_kernel<<<BT, 128>>>(h, ln1s + i*EMB, ln1b + i*EMB, y);

        qkv_gemm<<<dim3(12, M/128), 256, GEMM_SMEM_BYTES>>>(
            y, Wqi, Wki, Wvi, bq + i*EMB, bk + i*EMB, bv + i*EMB, q, k, v);

        attn_mma_kernel<<<dim3(NQT/2, NHEAD, BATCH), 128, ATT_SMEM_BYTES>>>(q, k, v, o);

        gemm128<false,true,0><<<dim3(EMB/128, M/128), 256, GEMM_SMEM_BYTES>>>(
            M, EMB, EMB, o, Woi, bo + i*EMB, h, nullptr);

        ln_kernel<<<BT, 128>>>(h, ln2s + i*EMB, ln2b + i*EMB, y);

        gemm128<true,false,1><<<dim3(FFDIM/128, M/128), 256, GEMM_SMEM_BYTES>>>(
            M, FFDIM, EMB, y, W1i, b1 + i*FFDIM, nullptr, ff);

        if (i < NLAYER - 1) {
            gemm128<false,true,0><<<dim3(EMB/128, M/128), 256, GEMM_SMEM_BYTES>>>(
                M, EMB, FFDIM, ff, W2i, b2 + i*EMB, h, nullptr);
        } else {
            gemm128<false,true,2><<<dim3(EMB/128, M/128), 256, GEMM_SMEM_BYTES>>>(
                M, EMB, FFDIM, ff, W2i, b2 + i*EMB, h, htf);
        }
    }

    gemm128<false,false,0><<<dim3(VOCAB/128, M/128), 256, GEMM_SMEM_BYTES>>>(
        M, VOCAB, EMB, htf, wtf + OFF_WOUT, bout, out, nullptr);
}

// round 12
// speedup vs baseline: 1.5212x; 1.0088x over previous
#include <cuda_runtime.h>
#include <cuda_bf16.h>
#include <math.h>
#include <stdint.h>

// ---------------- problem constants ----------------
#define VOCAB 32000
#define EMB   512
#define SEQ   2048
#define NHEAD 8
#define NLAYER 6
#define FFDIM 2048
#define BATCH 2
#define HEADD 64
#define BT    (BATCH*SEQ)      // 4096 tokens
#define EPS_LN 1e-5f

// ---------------- scratch (device globals; no allocation allowed) ----------------
__device__ float    g_h  [BT*EMB];     // residual stream (fp32)
__device__ uint32_t g_y  [BT*EMB];     // LN output (tf32)
__device__ uint32_t g_q  [BT*EMB];     // tf32, pre-scaled by 0.125
__device__ uint32_t g_k  [BT*EMB];     // tf32
__device__ uint32_t g_v  [BT*EMB];     // tf32
__device__ uint32_t g_o  [BT*EMB];     // attention output (tf32)
__device__ uint32_t g_ff [BT*FFDIM];   // FFN hidden (tf32)
__device__ uint32_t g_htf[BT*EMB];     // final residual (tf32) for vocab gemm

// tf32 weight mirror, same [K][N] layout as inputs
#define EE6 (NLAYER*EMB*EMB)
#define EF6 (NLAYER*EMB*FFDIM)
#define OFF_WQ   0
#define OFF_WK   (EE6)
#define OFF_WV   (2*EE6)
#define OFF_WO   (3*EE6)
#define OFF_W1   (4*EE6)
#define OFF_W2   (4*EE6 + EF6)
#define OFF_WOUT (4*EE6 + 2*EF6)
#define WTF_TOTAL (4*EE6 + 2*EF6 + EMB*VOCAB)
__device__ uint32_t g_wtf[WTF_TOTAL];

// ---------------- helpers ----------------
__device__ __forceinline__ uint32_t f2tf(float f) {
    uint32_t u; asm("cvt.rna.tf32.f32 %0, %1;" : "=r"(u) : "f"(f)); return u;
}
__device__ __forceinline__ void mma_tf32(float* c, const uint32_t* a, const uint32_t* b) {
    asm volatile(
        "mma.sync.aligned.m16n8k8.row.col.f32.tf32.tf32.f32 "
        "{%0,%1,%2,%3}, {%4,%5,%6,%7}, {%8,%9}, {%0,%1,%2,%3};\n"
        : "+f"(c[0]), "+f"(c[1]), "+f"(c[2]), "+f"(c[3])
        : "r"(a[0]), "r"(a[1]), "r"(a[2]), "r"(a[3]),
          "r"(b[0]), "r"(b[1]));
}
__device__ __forceinline__ uint32_t smem_u32(const void* p) {
    uint32_t a;
    asm("{ .reg .u64 t; cvta.to.shared.u64 t, %1; cvt.u32.u64 %0, t; }" : "=r"(a) : "l"(p));
    return a;
}
#define CP_ASYNC16(dst, src) \
    asm volatile("cp.async.cg.shared.global [%0], [%1], 16;" :: "r"(dst), "l"(src))
#define CP_COMMIT() asm volatile("cp.async.commit_group;" ::: "memory")
#define CP_WAIT1()  asm volatile("cp.async.wait_group 1;" ::: "memory")
#define CP_WAIT0()  asm volatile("cp.async.wait_group 0;" ::: "memory")

// ---------------- one-time weight convert fp32 -> tf32 ----------------
__global__ void cvt_tf_kernel(const float* __restrict__ s, uint32_t* __restrict__ d, int n)
{
    int i = (blockIdx.x * 256 + threadIdx.x) * 4;
    if (i < n) {
        float4 v = *(const float4*)&s[i];
        uint4 u = { f2tf(v.x), f2tf(v.y), f2tf(v.z), f2tf(v.w) };
        *(uint4*)&d[i] = u;
    }
}

// ---------------- embedding ----------------
__global__ void embed_kernel(const int* __restrict__ x,
                             const float* __restrict__ tok,
                             const float* __restrict__ pos,
                             float* __restrict__ h)
{
    int row = blockIdx.x;
    int t   = row % SEQ;
    int id  = x[row];
    const float* te = tok + (size_t)id * EMB;
    const float* pe = pos + (size_t)t  * EMB;
    float* out = h + (size_t)row * EMB;
    for (int i = threadIdx.x; i < EMB; i += blockDim.x)
        out[i] = te[i] + pe[i];
}

// ---------------- layernorm: one warp per row, shuffle-only ----------------
__global__ __launch_bounds__(256) void ln_kernel(
    const float* __restrict__ X,
    const float* __restrict__ scale,
    const float* __restrict__ bias,
    uint32_t* __restrict__ Y)
{
    const int warp = threadIdx.x >> 5, lane = threadIdx.x & 31;
    const int row  = blockIdx.x * 8 + warp;
    const float* x = X + (size_t)row * EMB;
    uint32_t*    y = Y + (size_t)row * EMB;

    float4 v[4];
    float s = 0.f, sq = 0.f;
    #pragma unroll
    for (int i = 0; i < 4; i++) {
        v[i] = *(const float4*)&x[lane*4 + i*128];
        s  += v[i].x + v[i].y + v[i].z + v[i].w;
        sq += v[i].x*v[i].x + v[i].y*v[i].y + v[i].z*v[i].z + v[i].w*v[i].w;
    }
    #pragma unroll
    for (int d = 16; d > 0; d >>= 1) {
        s  += __shfl_xor_sync(0xffffffffu, s,  d);
        sq += __shfl_xor_sync(0xffffffffu, sq, d);
    }
    float mean = s * (1.0f/EMB);
    float var  = sq * (1.0f/EMB) - mean*mean;
    float rstd = rsqrtf(var + EPS_LN);

    #pragma unroll
    for (int i = 0; i < 4; i++) {
        float4 sc = *(const float4*)&scale[lane*4 + i*128];
        float4 bb = *(const float4*)&bias [lane*4 + i*128];
        uint4 u;
        u.x = f2tf((v[i].x - mean)*rstd*sc.x + bb.x);
        u.y = f2tf((v[i].y - mean)*rstd*sc.y + bb.y);
        u.z = f2tf((v[i].z - mean)*rstd*sc.z + bb.z);
        u.w = f2tf((v[i].w - mean)*rstd*sc.w + bb.w);
        *(uint4*)&y[lane*4 + i*128] = u;
    }
}

// ---------------- tf32 GEMM, cp.async 3-stage, single barrier per k-tile ----------------
#define APAD 36
#define WPAD 136
#define STG_WORDS (128*APAD + 32*WPAD)
#define NSTAGE 3
#define GEMM_SMEM_BYTES (NSTAGE*STG_WORDS*4)   // 107520 B

template<bool RELU, bool RES, int TFM>
__device__ __forceinline__ void gemm_core(
    const uint32_t* __restrict__ A,
    const uint32_t* __restrict__ W,
    const float* __restrict__ bias,
    float* __restrict__ C,
    uint32_t* __restrict__ Ctf,
    float tfscale,
    int M, int N, int K, int bx, int by, uint32_t* dsm)
{
    const int tid  = threadIdx.x;
    const int warp = tid >> 5, lane = tid & 31;
    const int m0   = (warp & 1) * 64;
    const int n0   = (warp >> 1) * 32;
    const int group = lane >> 2, tcol = lane & 3;

    const int aRow = tid >> 3;
    const int aCol = (tid & 7) << 2;
    const int wRow = tid >> 3;
    const int wCol = (tid & 7) << 2;

    const uint32_t smb = smem_u32(dsm);
    const uint32_t aDst = smb + (uint32_t)(aRow*APAD + aCol)*4;
    const uint32_t wDst = smb + (uint32_t)(128*APAD + wRow*WPAD + wCol)*4;

    float c[4][4][4];
    #pragma unroll
    for (int mt = 0; mt < 4; mt++)
        #pragma unroll
        for (int nt = 0; nt < 4; nt++)
            #pragma unroll
            for (int j = 0; j < 4; j++) c[mt][nt][j] = 0.f;

    const int ktiles = K >> 5;

    #define ISSUE_STAGE(kt_) do {                                              \
        const int _kb = (kt_) << 5;                                            \
        const uint32_t _so = (uint32_t)(((kt_) % NSTAGE) * STG_WORDS * 4);     \
        _Pragma("unroll")                                                      \
        for (int i = 0; i < 4; i++)                                            \
            CP_ASYNC16(aDst + _so + (uint32_t)(i*32*APAD)*4,                   \
                       &A[(size_t)(by*128 + aRow + i*32)*K + _kb + aCol]);     \
        _Pragma("unroll")                                                      \
        for (int i = 0; i < 4; i++)                                            \
            CP_ASYNC16(wDst + _so + (uint32_t)(i*32)*4,                        \
                       &W[(size_t)(_kb + wRow)*N + bx*128 + wCol + i*32]);     \
    } while (0)

    ISSUE_STAGE(0); CP_COMMIT();
    ISSUE_STAGE(1); CP_COMMIT();

    for (int kt = 0; kt < ktiles; kt++) {
        CP_WAIT1();
        __syncthreads();

        if (kt + 2 < ktiles) ISSUE_STAGE(kt + 2);
        CP_COMMIT();

        const uint32_t* Ass = dsm + (kt % NSTAGE)*STG_WORDS;
        const uint32_t* Wss = Ass + 128*APAD;

        #pragma unroll
        for (int ks = 0; ks < 4; ks++) {
            const int k0 = ks << 3;
            uint32_t af[4][4], bf[4][2];
            #pragma unroll
            for (int mt = 0; mt < 4; mt++) {
                const int mb = m0 + mt*16 + group;
                af[mt][0] = Ass[(mb    )*APAD + k0 + tcol];
                af[mt][1] = Ass[(mb + 8)*APAD + k0 + tcol];
                af[mt][2] = Ass[(mb    )*APAD + k0 + tcol + 4];
                af[mt][3] = Ass[(mb + 8)*APAD + k0 + tcol + 4];
            }
            #pragma unroll
            for (int nt = 0; nt < 4; nt++) {
                const int nb = n0 + nt*8 + group;
                bf[nt][0] = Wss[(k0 + tcol    )*WPAD + nb];
                bf[nt][1] = Wss[(k0 + tcol + 4)*WPAD + nb];
            }
            #pragma unroll
            for (int mt = 0; mt < 4; mt++)
                #pragma unroll
                for (int nt = 0; nt < 4; nt++)
                    mma_tf32(c[mt][nt], af[mt], bf[nt]);
        }
    }
    #undef ISSUE_STAGE

    #pragma unroll
    for (int mt = 0; mt < 4; mt++) {
        #pragma unroll
        for (int nt = 0; nt < 4; nt++) {
            const int col = bx*128 + n0 + nt*8 + tcol*2;
            float2 bb = *(const float2*)&bias[col];
            #pragma unroll
            for (int r = 0; r < 2; r++) {
                const int row = by*128 + m0 + mt*16 + group + r*8;
                float2 v;
                v.x = c[mt][nt][r*2+0] + bb.x;
                v.y = c[mt][nt][r*2+1] + bb.y;
                if (RELU) { v.x = fmaxf(v.x, 0.f); v.y = fmaxf(v.y, 0.f); }
                float2* cp = (float2*)&C[(size_t)row*N + col];
                if (RES) { float2 o = *cp; v.x += o.x; v.y += o.y; }
                if (TFM != 1) *cp = v;
                if (TFM >= 1) {
                    uint2 t2 = { f2tf(v.x * tfscale), f2tf(v.y * tfscale) };
                    *(uint2*)&Ctf[(size_t)row*N + col] = t2;
                }
            }
        }
    }
}

template<bool RELU, bool RES, int TFM>
__global__ __launch_bounds__(256, 2) void gemm128(
    int M, int N, int K,
    const uint32_t* __restrict__ A,
    const uint32_t* __restrict__ W,
    const float* __restrict__ bias,
    float* __restrict__ C,
    uint32_t* __restrict__ Ctf)
{
    extern __shared__ uint32_t dsm[];
    gemm_core<RELU,RES,TFM>(A, W, bias, C, Ctf, 1.0f, M, N, K, blockIdx.x, blockIdx.y, dsm);
}

__global__ __launch_bounds__(256, 2) void qkv_gemm(
    const uint32_t* __restrict__ A,
    const uint32_t* __restrict__ Wq, const uint32_t* __restrict__ Wk, const uint32_t* __restrict__ Wv,
    const float* __restrict__ bq, const float* __restrict__ bk, const float* __restrict__ bv,
    uint32_t* __restrict__ q, uint32_t* __restrict__ k, uint32_t* __restrict__ v)
{
    extern __shared__ uint32_t dsm[];
    const int w   = blockIdx.x >> 2;
    const int nbx = blockIdx.x & 3;
    const uint32_t* W = (w == 0) ? Wq : (w == 1) ? Wk : Wv;
    const float*    b = (w == 0) ? bq : (w == 1) ? bk : bv;
    uint32_t*       C = (w == 0) ? q  : (w == 1) ? k  : v;
    const float    sc = (w == 0) ? 0.125f : 1.0f;
    gemm_core<false,false,1>(A, W, b, nullptr, C, sc, BT, EMB, EMB, nbx, blockIdx.y, dsm);
}

// ---------------- gemm64: 64x128 tile for single-wave GEMMs (o-proj, FF2) ----------------
// 256 threads = 8 warps as 2(M)x4(N); warp tile 32x32 = 2x4 mma tiles.
#define STG64_WORDS (64*APAD + 32*WPAD)        // 6656 words / stage
#define GEMM64_SMEM_BYTES (NSTAGE*STG64_WORDS*4)   // 79872 B

template<bool RELU, bool RES, int TFM>
__global__ __launch_bounds__(256, 2) void gemm64(
    int M, int N, int K,
    const uint32_t* __restrict__ A,
    const uint32_t* __restrict__ W,
    const float* __restrict__ bias,
    float* __restrict__ C,
    uint32_t* __restrict__ Ctf)
{
    extern __shared__ uint32_t dsm[];
    const int bx = blockIdx.x, by = blockIdx.y;
    const int tid  = threadIdx.x;
    const int warp = tid >> 5, lane = tid & 31;
    const int m0   = (warp & 1) * 32;
    const int n0   = (warp >> 1) * 32;
    const int group = lane >> 2, tcol = lane & 3;

    const int aRow = tid >> 3;          // 0..31 (+32)
    const int aCol = (tid & 7) << 2;
    const int wRow = tid >> 3;
    const int wCol = (tid & 7) << 2;

    const uint32_t smb = smem_u32(dsm);
    const uint32_t aDst = smb + (uint32_t)(aRow*APAD + aCol)*4;
    const uint32_t wDst = smb + (uint32_t)(64*APAD + wRow*WPAD + wCol)*4;

    float c[2][4][4];
    #pragma unroll
    for (int mt = 0; mt < 2; mt++)
        #pragma unroll
        for (int nt = 0; nt < 4; nt++)
            #pragma unroll
            for (int j = 0; j < 4; j++) c[mt][nt][j] = 0.f;

    const int ktiles = K >> 5;

    #define ISSUE64(kt_) do {                                                  \
        const int _kb = (kt_) << 5;                                            \
        const uint32_t _so = (uint32_t)(((kt_) % NSTAGE) * STG64_WORDS * 4);   \
        _Pragma("unroll")                                                      \
        for (int i = 0; i < 2; i++)                                            \
            CP_ASYNC16(aDst + _so + (uint32_t)(i*32*APAD)*4,                   \
                       &A[(size_t)(by*64 + aRow + i*32)*K + _kb + aCol]);      \
        _Pragma("unroll")                                                      \
        for (int i = 0; i < 4; i++)                                            \
            CP_ASYNC16(wDst + _so + (uint32_t)(i*32)*4,                        \
                       &W[(size_t)(_kb + wRow)*N + bx*128 + wCol + i*32]);     \
    } while (0)

    ISSUE64(0); CP_COMMIT();
    ISSUE64(1); CP_COMMIT();

    for (int kt = 0; kt < ktiles; kt++) {
        CP_WAIT1();
        __syncthreads();

        if (kt + 2 < ktiles) ISSUE64(kt + 2);
        CP_COMMIT();

        const uint32_t* Ass = dsm + (kt % NSTAGE)*STG64_WORDS;
        const uint32_t* Wss = Ass + 64*APAD;

        #pragma unroll
        for (int ks = 0; ks < 4; ks++) {
            const int k0 = ks << 3;
            uint32_t af[2][4], bf[4][2];
            #pragma unroll
            for (int mt = 0; mt < 2; mt++) {
                const int mb = m0 + mt*16 + group;
                af[mt][0] = Ass[(mb    )*APAD + k0 + tcol];
                af[mt][1] = Ass[(mb + 8)*APAD + k0 + tcol];
                af[mt][2] = Ass[(mb    )*APAD + k0 + tcol + 4];
                af[mt][3] = Ass[(mb + 8)*APAD + k0 + tcol + 4];
            }
            #pragma unroll
            for (int nt = 0; nt < 4; nt++) {
                const int nb = n0 + nt*8 + group;
                bf[nt][0] = Wss[(k0 + tcol    )*WPAD + nb];
                bf[nt][1] = Wss[(k0 + tcol + 4)*WPAD + nb];
            }
            #pragma unroll
            for (int mt = 0; mt < 2; mt++)
                #pragma unroll
                for (int nt = 0; nt < 4; nt++)
                    mma_tf32(c[mt][nt], af[mt], bf[nt]);
        }
    }
    #undef ISSUE64

    #pragma unroll
    for (int mt = 0; mt < 2; mt++) {
        #pragma unroll
        for (int nt = 0; nt < 4; nt++) {
            const int col = bx*128 + n0 + nt*8 + tcol*2;
            float2 bb = *(const float2*)&bias[col];
            #pragma unroll
            for (int r = 0; r < 2; r++) {
                const int row = by*64 + m0 + mt*16 + group + r*8;
                float2 v;
                v.x = c[mt][nt][r*2+0] + bb.x;
                v.y = c[mt][nt][r*2+1] + bb.y;
                if (RELU) { v.x = fmaxf(v.x, 0.f); v.y = fmaxf(v.y, 0.f); }
                float2* cp = (float2*)&C[(size_t)row*N + col];
                if (RES) { float2 o = *cp; v.x += o.x; v.y += o.y; }
                if (TFM != 1) *cp = v;
                if (TFM >= 1) {
                    uint2 t2 = { f2tf(v.x), f2tf(v.y) };
                    *(uint2*)&Ctf[(size_t)row*N + col] = t2;
                }
            }
        }
    }
}

// ---------------- flash attention: diagonal-paired 64-query tiles (unchanged) ----------------
#define QS_STRIDE 68
#define KS_STRIDE 68
#define VS_STRIDE 72
#define PS_STRIDE 68
#define KV_WORDS  (64*KS_STRIDE + 64*VS_STRIDE)
#define ATT_SMEM_WORDS (64*QS_STRIDE + 2*KV_WORDS)
#define ATT_SMEM_BYTES (ATT_SMEM_WORDS*4)          // 89088 B -> 2 CTAs/SM

#define NQT (SEQ/64)

__global__ __launch_bounds__(128, 2) void attn_mma_kernel(
        const uint32_t* __restrict__ Q,
        const uint32_t* __restrict__ K,
        const uint32_t* __restrict__ V,
        uint32_t* __restrict__ O)
{
    extern __shared__ uint32_t smw[];
    uint32_t* qs  = smw;
    uint32_t* kv0 = qs + 64*QS_STRIDE;
    uint32_t* ps  = qs;

    const int pair = blockIdx.x, hh = blockIdx.y, bb = blockIdx.z;
    const int tid = threadIdx.x, warp = tid >> 5, lane = tid & 31;
    const int g = lane >> 2, tc = lane & 3;
    const int wq = warp * 16;

    const size_t base = ((size_t)bb*SEQ)*EMB + (size_t)hh*HEADD;
    const uint32_t kvb = smem_u32(kv0);

    const int tok0 = tid >> 4;
    const int d4s  = (tid & 15) << 2;

    #define ATT_ISSUE(kt_) do {                                                     \
        const uint32_t _so = (uint32_t)(((kt_) & 1) * KV_WORDS * 4);                \
        _Pragma("unroll")                                                           \
        for (int i = 0; i < 8; i++) {                                               \
            int _tok = tok0 + i*8;                                                  \
            CP_ASYNC16(kvb + _so + (uint32_t)(_tok*KS_STRIDE + d4s)*4,              \
                       &K[base + (size_t)((kt_)*64 + _tok)*EMB + d4s]);             \
            CP_ASYNC16(kvb + _so + (uint32_t)(64*KS_STRIDE + _tok*VS_STRIDE + d4s)*4,\
                       &V[base + (size_t)((kt_)*64 + _tok)*EMB + d4s]);             \
        }                                                                           \
    } while (0)

    for (int phase = 0; phase < 2; phase++) {
        const int qt  = phase ? (NQT - 1 - pair) : pair;
        const int nkt = qt + 1;

        #pragma unroll
        for (int i = 0; i < 8; i++) {
            int f   = i*128 + tid;
            int row = f >> 4, d4 = (f & 15) << 2;
            *(uint4*)&qs[row*QS_STRIDE + d4] =
                *(const uint4*)&Q[base + (size_t)(qt*64 + row)*EMB + d4];
        }
        ATT_ISSUE(0); CP_COMMIT();
        __syncthreads();

        uint32_t qf[8][4];
        #pragma unroll
        for (int ki = 0; ki < 8; ki++) {
            int k0 = ki*8;
            qf[ki][0] = qs[(wq+g  )*QS_STRIDE + k0 + tc];
            qf[ki][1] = qs[(wq+g+8)*QS_STRIDE + k0 + tc];
            qf[ki][2] = qs[(wq+g  )*QS_STRIDE + k0 + tc + 4];
            qf[ki][3] = qs[(wq+g+8)*QS_STRIDE + k0 + tc + 4];
        }

        float o[8][4];
        #pragma unroll
        for (int nt = 0; nt < 8; nt++)
            #pragma unroll
            for (int j = 0; j < 4; j++) o[nt][j] = 0.f;
        float m0 = -1e30f, m1 = -1e30f, l0 = 0.f, l1 = 0.f;

        for (int kt = 0; kt < nkt; kt++) {
            if (kt + 1 < nkt) { ATT_ISSUE(kt + 1); CP_COMMIT(); CP_WAIT1(); }
            else              { CP_WAIT0(); }
            __syncthreads();

            const uint32_t* ks = kv0 + (kt & 1)*KV_WORDS;
            const uint32_t* vs = ks + 64*KS_STRIDE;

            float sc[8][4];
            #pragma unroll
            for (int nt = 0; nt < 8; nt++)
                #pragma unroll
                for (int j = 0; j < 4; j++) sc[nt][j] = 0.f;

            #pragma unroll
            for (int ki = 0; ki < 8; ki++) {
                int k0 = ki*8;
                uint32_t bf[8][2];
                #pragma unroll
                for (int nt = 0; nt < 8; nt++) {
                    int nb = nt*8 + g;
                    bf[nt][0] = ks[nb*KS_STRIDE + k0 + tc];
                    bf[nt][1] = ks[nb*KS_STRIDE + k0 + tc + 4];
                }
                #pragma unroll
                for (int nt = 0; nt < 8; nt++)
                    mma_tf32(sc[nt], qf[ki], bf[nt]);
            }

            if (kt >= qt) {
                const int row0 = qt*64 + wq + g;
                #pragma unroll
                for (int nt = 0; nt < 8; nt++) {
                    int c0 = kt*64 + nt*8 + 2*tc;
                    if (c0     > row0    ) sc[nt][0] = -1e30f;
                    if (c0 + 1 > row0    ) sc[nt][1] = -1e30f;
                    if (c0     > row0 + 8) sc[nt][2] = -1e30f;
                    if (c0 + 1 > row0 + 8) sc[nt][3] = -1e30f;
                }
            }

            float r0 = -1e30f, r1 = -1e30f;
            #pragma unroll
            for (int nt = 0; nt < 8; nt++) {
                r0 = fmaxf(r0, fmaxf(sc[nt][0], sc[nt][1]));
                r1 = fmaxf(r1, fmaxf(sc[nt][2], sc[nt][3]));
            }
            r0 = fmaxf(r0, __shfl_xor_sync(0xffffffffu, r0, 1));
            r0 = fmaxf(r0, __shfl_xor_sync(0xffffffffu, r0, 2));
            r1 = fmaxf(r1, __shfl_xor_sync(0xffffffffu, r1, 1));
            r1 = fmaxf(r1, __shfl_xor_sync(0xffffffffu, r1, 2));

            float mn0 = fmaxf(m0, r0), mn1 = fmaxf(m1, r1);
            float cor0 = __expf(m0 - mn0), cor1 = __expf(m1 - mn1);
            m0 = mn0; m1 = mn1;
            l0 *= cor0; l1 *= cor1;
            #pragma unroll
            for (int nt = 0; nt < 8; nt++) {
                o[nt][0] *= cor0; o[nt][1] *= cor0;
                o[nt][2] *= cor1; o[nt][3] *= cor1;
            }

            float s0 = 0.f, s1 = 0.f;
            #pragma unroll
            for (int nt = 0; nt < 8; nt++) {
                float p00 = __expf(sc[nt][0] - mn0);
                float p01 = __expf(sc[nt][1] - mn0);
                float p10 = __expf(sc[nt][2] - mn1);
                float p11 = __expf(sc[nt][3] - mn1);
                s0 += p00 + p01; s1 += p10 + p11;
                int col = nt*8 + 2*tc;
                ps[(wq+g  )*PS_STRIDE + col    ] = f2tf(p00);
                ps[(wq+g  )*PS_STRIDE + col + 1] = f2tf(p01);
                ps[(wq+g+8)*PS_STRIDE + col    ] = f2tf(p10);
                ps[(wq+g+8)*PS_STRIDE + col + 1] = f2tf(p11);
            }
            s0 += __shfl_xor_sync(0xffffffffu, s0, 1);
            s0 += __shfl_xor_sync(0xffffffffu, s0, 2);
            s1 += __shfl_xor_sync(0xffffffffu, s1, 1);
            s1 += __shfl_xor_sync(0xffffffffu, s1, 2);
            l0 += s0; l1 += s1;
            __syncwarp();

            #pragma unroll
            for (int ki = 0; ki < 8; ki++) {
                int k0 = ki*8;
                uint32_t af[4];
                af[0] = ps[(wq+g  )*PS_STRIDE + k0 + tc];
                af[1] = ps[(wq+g+8)*PS_STRIDE + k0 + tc];
                af[2] = ps[(wq+g  )*PS_STRIDE + k0 + tc + 4];
                af[3] = ps[(wq+g+8)*PS_STRIDE + k0 + tc + 4];
                uint32_t bf[8][2];
                #pragma unroll
                for (int nt = 0; nt < 8; nt++) {
                    int nb = nt*8 + g;
                    bf[nt][0] = vs[(k0 + tc    )*VS_STRIDE + nb];
                    bf[nt][1] = vs[(k0 + tc + 4)*VS_STRIDE + nb];
                }
                #pragma unroll
                for (int nt = 0; nt < 8; nt++)
                    mma_tf32(o[nt], af, bf[nt]);
            }
            __syncthreads();
        }

        float inv0 = 1.0f / l0, inv1 = 1.0f / l1;
        const int row0 = qt*64 + wq + g;
        #pragma unroll
        for (int nt = 0; nt < 8; nt++) {
            int d = nt*8 + 2*tc;
            uint2 a = { f2tf(o[nt][0]*inv0), f2tf(o[nt][1]*inv0) };
            *(uint2*)&O[base + (size_t)row0*EMB + d] = a;
            uint2 b = { f2tf(o[nt][2]*inv1), f2tf(o[nt][3]*inv1) };
            *(uint2*)&O[base + (size_t)(row0+8)*EMB + d] = b;
        }
        __syncthreads();
    }
    #undef ATT_ISSUE
}

// ---------------- orchestration ----------------
extern "C" void kernel_launch(void* const* d_in, const int* in_sizes, int n_in,
                              void* d_out, int out_size)
{
    (void)in_sizes; (void)n_in;
    const int*   x       = (const int*)  d_in[0];
    const float* tok_emb = (const float*)d_in[1];
    const float* pos_emb = (const float*)d_in[2];
    const float* Wq   = (const float*)d_in[3];
    const float* bq   = (const float*)d_in[4];
    const float* Wk   = (const float*)d_in[5];
    const float* bk   = (const float*)d_in[6];
    const float* Wv   = (const float*)d_in[7];
    const float* bv   = (const float*)d_in[8];
    const float* Wo   = (const float*)d_in[9];
    const float* bo   = (const float*)d_in[10];
    const float* ln1s = (const float*)d_in[11];
    const float* ln1b = (const float*)d_in[12];
    const float* ln2s = (const float*)d_in[13];
    const float* ln2b = (const float*)d_in[14];
    const float* W1   = (const float*)d_in[15];
    const float* b1   = (const float*)d_in[16];
    const float* W2   = (const float*)d_in[17];
    const float* b2   = (const float*)d_in[18];
    const float* Wout = (const float*)d_in[19];
    const float* bout = (const float*)d_in[20];
    float* out = (float*)d_out;
    (void)out_size;

    float *h; uint32_t *y, *q, *k, *v, *o, *ff, *htf, *wtf;
    cudaGetSymbolAddress((void**)&h,   g_h);
    cudaGetSymbolAddress((void**)&y,   g_y);
    cudaGetSymbolAddress((void**)&q,   g_q);
    cudaGetSymbolAddress((void**)&k,   g_k);
    cudaGetSymbolAddress((void**)&v,   g_v);
    cudaGetSymbolAddress((void**)&o,   g_o);
    cudaGetSymbolAddress((void**)&ff,  g_ff);
    cudaGetSymbolAddress((void**)&htf, g_htf);
    cudaGetSymbolAddress((void**)&wtf, g_wtf);

    cudaFuncSetAttribute(gemm128<false,false,0>,
        cudaFuncAttributeMaxDynamicSharedMemorySize, GEMM_SMEM_BYTES);
    cudaFuncSetAttribute(gemm128<true,false,1>,
        cudaFuncAttributeMaxDynamicSharedMemorySize, GEMM_SMEM_BYTES);
    cudaFuncSetAttribute(qkv_gemm,
        cudaFuncAttributeMaxDynamicSharedMemorySize, GEMM_SMEM_BYTES);
    cudaFuncSetAttribute(gemm64<false,true,0>,
        cudaFuncAttributeMaxDynamicSharedMemorySize, GEMM64_SMEM_BYTES);
    cudaFuncSetAttribute(gemm64<false,true,2>,
        cudaFuncAttributeMaxDynamicSharedMemorySize, GEMM64_SMEM_BYTES);
    cudaFuncSetAttribute(attn_mma_kernel,
        cudaFuncAttributeMaxDynamicSharedMemorySize, ATT_SMEM_BYTES);

    // ---- one-time weight conversion to tf32 ----
    {
        const int T = 256;
        cvt_tf_kernel<<<EE6/(4*T), T>>>(Wq,   wtf + OFF_WQ,   EE6);
        cvt_tf_kernel<<<EE6/(4*T), T>>>(Wk,   wtf + OFF_WK,   EE6);
        cvt_tf_kernel<<<EE6/(4*T), T>>>(Wv,   wtf + OFF_WV,   EE6);
        cvt_tf_kernel<<<EE6/(4*T), T>>>(Wo,   wtf + OFF_WO,   EE6);
        cvt_tf_kernel<<<EF6/(4*T), T>>>(W1,   wtf + OFF_W1,   EF6);
        cvt_tf_kernel<<<EF6/(4*T), T>>>(W2,   wtf + OFF_W2,   EF6);
        cvt_tf_kernel<<<(EMB*VOCAB)/(4*T), T>>>(Wout, wtf + OFF_WOUT, EMB*VOCAB);
    }

    const int M = BT;
    embed_kernel<<<BT, 128>>>(x, tok_emb, pos_emb, h);

    for (int i = 0; i < NLAYER; i++) {
        const uint32_t* Wqi = wtf + OFF_WQ + (size_t)i*EMB*EMB;
        const uint32_t* Wki = wtf + OFF_WK + (size_t)i*EMB*EMB;
        const uint32_t* Wvi = wtf + OFF_WV + (size_t)i*EMB*EMB;
        const uint32_t* Woi = wtf + OFF_WO + (size_t)i*EMB*EMB;
        const uint32_t* W1i = wtf + OFF_W1 + (size_t)i*EMB*FFDIM;
        const uint32_t* W2i = wtf + OFF_W2 + (size_t)i*FFDIM*EMB;

        ln_kernel<<<BT/8, 256>>>(h, ln1s + i*EMB, ln1b + i*EMB, y);

        qkv_gemm<<<dim3(12, M/128), 256, GEMM_SMEM_BYTES>>>(
            y, Wqi, Wki, Wvi, bq + i*EMB, bk + i*EMB, bv + i*EMB, q, k, v);

        attn_mma_kernel<<<dim3(NQT/2, NHEAD, BATCH), 128, ATT_SMEM_BYTES>>>(q, k, v, o);

        gemm64<false,true,0><<<dim3(EMB/128, M/64), 256, GEMM64_SMEM_BYTES>>>(
            M, EMB, EMB, o, Woi, bo + i*EMB, h, nullptr);

        ln_kernel<<<BT/8, 256>>>(h, ln2s + i*EMB, ln2b + i*EMB, y);

        gemm128<true,false,1><<<dim3(FFDIM/128, M/128), 256, GEMM_SMEM_BYTES>>>(
            M, FFDIM, EMB, y, W1i, b1 + i*FFDIM, nullptr, ff);

        if (i < NLAYER - 1) {
            gemm64<false,true,0><<<dim3(EMB/128, M/64), 256, GEMM64_SMEM_BYTES>>>(
                M, EMB, FFDIM, ff, W2i, b2 + i*EMB, h, nullptr);
        } else {
            gemm64<false,true,2><<<dim3(EMB/128, M/64), 256, GEMM64_SMEM_BYTES>>>(
                M, EMB, FFDIM, ff, W2i, b2 + i*EMB, h, htf);
        }
    }

    gemm128<false,false,0><<<dim3(VOCAB/128, M/128), 256, GEMM_SMEM_BYTES>>>(
        M, VOCAB, EMB, htf, wtf + OFF_WOUT, bout, out, nullptr);
}